// round 7
// baseline (speedup 1.0000x reference)
#include <cuda_runtime.h>
#include <cuda_bf16.h>
#include <cstdint>

#define SQ 4096
#define EE 512
#define HH 8
#define DD 64
#define HSZ (SQ*DD)
#define TOT (SQ*EE)

// ------------------- global scratch -------------------
__device__ float g_vf[TOT];
__device__ __nv_bfloat16 g_Qhi[TOT], g_Qlo[TOT], g_Khi[TOT], g_Klo[TOT], g_Vhi[TOT], g_Vlo[TOT];
__device__ __nv_bfloat16 g_W1hi[EE*EE], g_W1lo[EE*EE];
__device__ __nv_bfloat16 g_W2hi[EE*EE], g_W2lo[EE*EE];
__device__ __nv_bfloat16 g_W3hi[EE*EE], g_W3lo[EE*EE];
__device__ __nv_bfloat16 g_qhi[TOT], g_qlo[TOT], g_khi[TOT], g_klo[TOT];
__device__ __nv_bfloat16 g_vthi[TOT], g_vtlo[TOT], g_ohi[TOT], g_olo[TOT];

// ------------------- helpers -------------------
__device__ __forceinline__ uint32_t smem_u32(const void* p) {
    uint32_t a;
    asm("{ .reg .u64 t; cvta.to.shared.u64 t, %1; cvt.u32.u64 %0, t; }" : "=r"(a) : "l"(p));
    return a;
}
#define LDSM4(R0,R1,R2,R3,ADDR) \
    asm volatile("ldmatrix.sync.aligned.m8n8.x4.shared.b16 {%0,%1,%2,%3}, [%4];" \
        : "=r"(R0),"=r"(R1),"=r"(R2),"=r"(R3) : "r"(ADDR))
#define MMA16816(C,A,B) \
    asm volatile("mma.sync.aligned.m16n8k16.row.col.f32.bf16.bf16.f32 " \
        "{%0,%1,%2,%3},{%4,%5,%6,%7},{%8,%9},{%0,%1,%2,%3};" \
        : "+f"((C)[0]),"+f"((C)[1]),"+f"((C)[2]),"+f"((C)[3]) \
        : "r"((A)[0]),"r"((A)[1]),"r"((A)[2]),"r"((A)[3]),"r"((B)[0]),"r"((B)[1]))
#define CPA16(DST,SRC) \
    asm volatile("cp.async.cg.shared.global [%0], [%1], 16;" :: "r"(DST), "l"(SRC) : "memory")
#define CPC() asm volatile("cp.async.commit_group;" ::: "memory")
#define CPW(N) asm volatile("cp.async.wait_group %0;" :: "n"(N) : "memory")
#define EX2(D,S) asm("ex2.approx.f32 %0, %1;" : "=f"(D) : "f"(S))

// ------------------- elementwise hi/lo split (3 tensors per launch) ----------
__global__ void split4x3(const float4* __restrict__ x0, uint2* __restrict__ h0, uint2* __restrict__ l0,
                         const float4* __restrict__ x1, uint2* __restrict__ h1, uint2* __restrict__ l1,
                         const float4* __restrict__ x2, uint2* __restrict__ h2, uint2* __restrict__ l2) {
    const float4* x = blockIdx.y == 0 ? x0 : blockIdx.y == 1 ? x1 : x2;
    uint2* hi = blockIdx.y == 0 ? h0 : blockIdx.y == 1 ? h1 : h2;
    uint2* lo = blockIdx.y == 0 ? l0 : blockIdx.y == 1 ? l1 : l2;
    int i = blockIdx.x * blockDim.x + threadIdx.x;
    float4 v = x[i];
    __nv_bfloat162 a01 = __floats2bfloat162_rn(v.x, v.y);
    __nv_bfloat162 a23 = __floats2bfloat162_rn(v.z, v.w);
    __nv_bfloat162 b01 = __floats2bfloat162_rn(v.x - __bfloat162float(a01.x),
                                               v.y - __bfloat162float(a01.y));
    __nv_bfloat162 b23 = __floats2bfloat162_rn(v.z - __bfloat162float(a23.x),
                                               v.w - __bfloat162float(a23.y));
    uint2 hv, lv;
    hv.x = *(uint32_t*)&a01; hv.y = *(uint32_t*)&a23;
    lv.x = *(uint32_t*)&b01; lv.y = *(uint32_t*)&b23;
    hi[i] = hv; lo[i] = lv;
}

// per-head transpose of V: [h][4096][64] -> [h][64][4096], split hi/lo
__global__ void vtrans_split(const float* __restrict__ vf,
                             __nv_bfloat16* __restrict__ vthi,
                             __nv_bfloat16* __restrict__ vtlo) {
    __shared__ float tile[32][33];
    int h = blockIdx.z, t0 = blockIdx.x * 32, d0 = blockIdx.y * 32;
    int tx = threadIdx.x, ty = threadIdx.y;
    tile[ty][tx] = vf[(size_t)h * HSZ + (size_t)(t0 + ty) * DD + d0 + tx];
    __syncthreads();
    float v = tile[tx][ty];
    __nv_bfloat16 hh = __float2bfloat16(v);
    __nv_bfloat16 ll = __float2bfloat16(v - __bfloat162float(hh));
    size_t o = (size_t)h * HSZ + (size_t)(d0 + ty) * SQ + t0 + tx;
    vthi[o] = hh; vtlo[o] = ll;
}

// ------------------- fused mma.sync GEMM (K-chunk 16, 3-stage, 2 CTA/SM) -----
#define GP16 48                          // 48B row pitch (24 bf16)
#define GMSZ (128*GP16)                  // 6144 B / matrix
#define GSTG (4*GMSZ)                    // 24576 B / stage
#define G_SMEM (3*GSTG)                  // 73728 B

struct GemmArgs {
    const __nv_bfloat16 *Ah[3], *Al[3], *Wh[3], *Wl[3];
    const float* bias[3];
    float* C[3];
    __nv_bfloat16 *Ch[3], *Cl[3];
    float scale[3];
};

__device__ __forceinline__ void gemm_prefetch16(
    uint32_t sbs, int tid, int m0, int n0, int ch,
    const __nv_bfloat16* Ah, const __nv_bfloat16* Al,
    const __nv_bfloat16* Wh, const __nv_bfloat16* Wl)
{
#pragma unroll
    for (int q = 0; q < 4; q++) {
        int id = q * 256 + tid;
        int mat = id >> 8, rem = id & 255, row = rem >> 1, col = rem & 1;
        const __nv_bfloat16* g =
            (mat == 0 ? Ah : mat == 1 ? Al : mat == 2 ? Wh : Wl)
            + (size_t)((mat < 2 ? m0 : n0) + row) * EE + ch * 16 + col * 8;
        CPA16(sbs + mat * GMSZ + row * GP16 + col * 16, g);
    }
}

__global__ void __launch_bounds__(256, 2) gemm_mma(GemmArgs ga)
{
    extern __shared__ char sm[];
    uint32_t sb = smem_u32(sm);
    int tid = threadIdx.x, wid = tid >> 5, lane = tid & 31;
    int wm = wid & 3, wn = wid >> 2;
    int m0 = blockIdx.y * 128, n0 = blockIdx.x * 128;
    int z = blockIdx.z;
    int l15 = lane & 15, lh = lane >> 4;

    const __nv_bfloat16 *Ah = ga.Ah[z], *Al = ga.Al[z], *Wh = ga.Wh[z], *Wl = ga.Wl[z];
    const float* bias = ga.bias[z];
    float* C = ga.C[z];
    __nv_bfloat16 *Chi = ga.Ch[z], *Clo = ga.Cl[z];
    float scale = ga.scale[z];

    float acc[2][8][4] = {};

    gemm_prefetch16(sb, tid, m0, n0, 0, Ah, Al, Wh, Wl); CPC();
    gemm_prefetch16(sb + GSTG, tid, m0, n0, 1, Ah, Al, Wh, Wl); CPC();

    for (int ch = 0; ch < 32; ch++) {
        if (ch == 31) { CPW(0); } else { CPW(1); }
        __syncthreads();
        if (ch + 2 < 32) {
            gemm_prefetch16(sb + ((ch + 2) % 3) * GSTG, tid, m0, n0, ch + 2, Ah, Al, Wh, Wl);
            CPC();
        }
        uint32_t sbs = sb + (ch % 3) * GSTG;

        uint32_t ah[2][4], al[2][4];
#pragma unroll
        for (int mt = 0; mt < 2; mt++) {
            uint32_t addr = sbs + (wm * 32 + mt * 16 + l15) * GP16 + lh * 16;
            LDSM4(ah[mt][0], ah[mt][1], ah[mt][2], ah[mt][3], addr);
            LDSM4(al[mt][0], al[mt][1], al[mt][2], al[mt][3], addr + GMSZ);
        }
#pragma unroll
        for (int jt = 0; jt < 4; jt++) {
            uint32_t addr = sbs + 2 * GMSZ + (wn * 64 + jt * 16 + l15) * GP16 + lh * 16;
            uint32_t h0, h1, h2, h3, l0, l1, l2, l3;
            LDSM4(h0, h1, h2, h3, addr);
            LDSM4(l0, l1, l2, l3, addr + GMSZ);
            uint32_t b0[2] = {h0, h2}, b1[2] = {h1, h3};
            uint32_t c0[2] = {l0, l2}, c1[2] = {l1, l3};
#pragma unroll
            for (int mt = 0; mt < 2; mt++) {
                MMA16816(acc[mt][2*jt],   ah[mt], b0);
                MMA16816(acc[mt][2*jt],   al[mt], b0);
                MMA16816(acc[mt][2*jt],   ah[mt], c0);
                MMA16816(acc[mt][2*jt+1], ah[mt], b1);
                MMA16816(acc[mt][2*jt+1], al[mt], b1);
                MMA16816(acc[mt][2*jt+1], ah[mt], c1);
            }
        }
    }

    int r = lane >> 2, c2 = (lane & 3) * 2;
#pragma unroll
    for (int mt = 0; mt < 2; mt++) {
        size_t rbase = (size_t)(m0 + wm * 32 + mt * 16 + r) * EE + n0 + wn * 64;
#pragma unroll
        for (int j = 0; j < 8; j++) {
            float b0 = __ldg(bias + n0 + wn * 64 + j * 8 + c2);
            float b1 = __ldg(bias + n0 + wn * 64 + j * 8 + c2 + 1);
            float y00 = (acc[mt][j][0] + b0) * scale, y01 = (acc[mt][j][1] + b1) * scale;
            float y10 = (acc[mt][j][2] + b0) * scale, y11 = (acc[mt][j][3] + b1) * scale;
            if (Chi) {
                __nv_bfloat162 h0 = __floats2bfloat162_rn(y00, y01);
                __nv_bfloat162 l0 = __floats2bfloat162_rn(y00 - __bfloat162float(h0.x),
                                                          y01 - __bfloat162float(h0.y));
                __nv_bfloat162 h1 = __floats2bfloat162_rn(y10, y11);
                __nv_bfloat162 l1 = __floats2bfloat162_rn(y10 - __bfloat162float(h1.x),
                                                          y11 - __bfloat162float(h1.y));
                *(uint32_t*)(Chi + rbase + j * 8 + c2)          = *(uint32_t*)&h0;
                *(uint32_t*)(Clo + rbase + j * 8 + c2)          = *(uint32_t*)&l0;
                *(uint32_t*)(Chi + rbase + 8 * EE + j * 8 + c2) = *(uint32_t*)&h1;
                *(uint32_t*)(Clo + rbase + 8 * EE + j * 8 + c2) = *(uint32_t*)&l1;
            } else {
                *(float2*)(C + rbase + j * 8 + c2)          = make_float2(y00, y01);
                *(float2*)(C + rbase + 8 * EE + j * 8 + c2) = make_float2(y10, y11);
            }
        }
    }
}

// ------------------- mma.sync flash attention (3-stage, 1 sync/chunk) --------
#define APITCH 72
#define AMSZ (64*APITCH*2)              // 9216 B / matrix
#define ASTG (4*AMSZ)                   // 36864 B / stage
#define A_SMEM (3*ASTG)                 // 110592 B

__device__ __forceinline__ void attn_prefetch(
    uint32_t sbs, int tid, size_t hb, int t0,
    const __nv_bfloat16* khi, const __nv_bfloat16* klo,
    const __nv_bfloat16* vth, const __nv_bfloat16* vtl)
{
#pragma unroll
    for (int q = 0; q < 8; q++) {
        int id = q * 256 + tid;
        int mat = id >> 9, rem = id & 511, row = rem >> 3, col = rem & 7;
        const __nv_bfloat16* g;
        if (mat == 0)      g = khi + hb + (size_t)(t0 + row) * DD + col * 8;
        else if (mat == 1) g = klo + hb + (size_t)(t0 + row) * DD + col * 8;
        else if (mat == 2) g = vth + hb + (size_t)row * SQ + t0 + col * 8;
        else               g = vtl + hb + (size_t)row * SQ + t0 + col * 8;
        CPA16(sbs + mat * AMSZ + row * (APITCH * 2) + col * 16, g);
    }
}

__global__ void __launch_bounds__(256, 2) attn_mma(
    const __nv_bfloat16* __restrict__ qhi, const __nv_bfloat16* __restrict__ qlo,
    const __nv_bfloat16* __restrict__ khi, const __nv_bfloat16* __restrict__ klo,
    const __nv_bfloat16* __restrict__ vth, const __nv_bfloat16* __restrict__ vtl,
    __nv_bfloat16* __restrict__ ohi, __nv_bfloat16* __restrict__ olo)
{
    extern __shared__ char sm[];
    uint32_t sb = smem_u32(sm);
    int tid = threadIdx.x, wid = tid >> 5, lane = tid & 31;
    int head = blockIdx.y, m0 = blockIdx.x * 128;
    const size_t hb = (size_t)head * HSZ;
    int r = lane >> 2, c2 = (lane & 3) * 2;
    int l15 = lane & 15, lh = lane >> 4;

    attn_prefetch(sb, tid, hb, 0, khi, klo, vth, vtl); CPC();
    attn_prefetch(sb + ASTG, tid, hb, 64, khi, klo, vth, vtl); CPC();

    // Q fragments (hi/lo), held in registers; q already scaled by 0.125*log2e
    uint32_t qh[4][4], ql[4][4];
    {
        const __nv_bfloat16* q0h = qhi + hb + (size_t)(m0 + wid * 16) * DD;
        const __nv_bfloat16* q0l = qlo + hb + (size_t)(m0 + wid * 16) * DD;
#pragma unroll
        for (int ks = 0; ks < 4; ks++)
#pragma unroll
            for (int j = 0; j < 4; j++) {
                int rr = r + (j & 1) * 8;
                int kk = ks * 16 + c2 + (j >> 1) * 8;
                qh[ks][j] = *(const uint32_t*)(q0h + rr * DD + kk);
                ql[ks][j] = *(const uint32_t*)(q0l + rr * DD + kk);
            }
    }

    float oacc[8][4] = {};
    float rs0 = 0.f, rs1 = 0.f;

    for (int t = 0; t < 64; t++) {
        if (t == 63) { CPW(0); } else { CPW(1); }
        __syncthreads();
        if (t + 2 < 64) {
            attn_prefetch(sb + ((t + 2) % 3) * ASTG, tid, hb, (t + 2) * 64, khi, klo, vth, vtl);
            CPC();
        }
        uint32_t sbs = sb + (t % 3) * ASTG;

        // ---- S = Q @ K^T (3-term) ----
        float sacc[8][4] = {};
#pragma unroll
        for (int ks = 0; ks < 4; ks++) {
#pragma unroll
            for (int jt = 0; jt < 4; jt++) {
                uint32_t addr = sbs + (jt * 16 + l15) * (APITCH * 2) + (ks * 16 + 8 * lh) * 2;
                uint32_t h0, h1, h2, h3, l0, l1, l2, l3;
                LDSM4(h0, h1, h2, h3, addr);
                LDSM4(l0, l1, l2, l3, addr + AMSZ);
                uint32_t b0[2] = {h0, h2}, b1[2] = {h1, h3};
                uint32_t c0[2] = {l0, l2}, c1[2] = {l1, l3};
                MMA16816(sacc[2*jt],   qh[ks], b0);
                MMA16816(sacc[2*jt],   ql[ks], b0);
                MMA16816(sacc[2*jt],   qh[ks], c0);
                MMA16816(sacc[2*jt+1], qh[ks], b1);
                MMA16816(sacc[2*jt+1], ql[ks], b1);
                MMA16816(sacc[2*jt+1], qh[ks], c1);
            }
        }

        // ---- softmax (exp2; scores pre-scaled by log2e) + PV per 16-kv slab ----
#pragma unroll
        for (int tt = 0; tt < 4; tt++) {
            float e0[4], e1[4];
#pragma unroll
            for (int e = 0; e < 4; e++) { EX2(e0[e], sacc[2*tt][e]); EX2(e1[e], sacc[2*tt+1][e]); }
            rs0 += e0[0] + e0[1] + e1[0] + e1[1];
            rs1 += e0[2] + e0[3] + e1[2] + e1[3];
            uint32_t pa[4], pl[4];
            {
                __nv_bfloat162 h, l;
                h = __floats2bfloat162_rn(e0[0], e0[1]);
                l = __floats2bfloat162_rn(e0[0] - __bfloat162float(h.x), e0[1] - __bfloat162float(h.y));
                pa[0] = *(uint32_t*)&h; pl[0] = *(uint32_t*)&l;
                h = __floats2bfloat162_rn(e0[2], e0[3]);
                l = __floats2bfloat162_rn(e0[2] - __bfloat162float(h.x), e0[3] - __bfloat162float(h.y));
                pa[1] = *(uint32_t*)&h; pl[1] = *(uint32_t*)&l;
                h = __floats2bfloat162_rn(e1[0], e1[1]);
                l = __floats2bfloat162_rn(e1[0] - __bfloat162float(h.x), e1[1] - __bfloat162float(h.y));
                pa[2] = *(uint32_t*)&h; pl[2] = *(uint32_t*)&l;
                h = __floats2bfloat162_rn(e1[2], e1[3]);
                l = __floats2bfloat162_rn(e1[2] - __bfloat162float(h.x), e1[3] - __bfloat162float(h.y));
                pa[3] = *(uint32_t*)&h; pl[3] = *(uint32_t*)&l;
            }
#pragma unroll
            for (int jt = 0; jt < 4; jt++) {
                uint32_t addr = sbs + 2 * AMSZ + (jt * 16 + l15) * (APITCH * 2)
                              + (tt * 16 + 8 * lh) * 2;
                uint32_t h0, h1, h2, h3, l0, l1, l2, l3;
                LDSM4(h0, h1, h2, h3, addr);
                LDSM4(l0, l1, l2, l3, addr + AMSZ);
                uint32_t b0[2] = {h0, h2}, b1[2] = {h1, h3};
                uint32_t c0[2] = {l0, l2}, c1[2] = {l1, l3};
                MMA16816(oacc[2*jt],   pa, b0);
                MMA16816(oacc[2*jt],   pl, b0);
                MMA16816(oacc[2*jt],   pa, c0);
                MMA16816(oacc[2*jt+1], pa, b1);
                MMA16816(oacc[2*jt+1], pl, b1);
                MMA16816(oacc[2*jt+1], pa, c1);
            }
        }
    }

    // rowsum reduce across the quad
    rs0 += __shfl_xor_sync(0xffffffffu, rs0, 1);
    rs0 += __shfl_xor_sync(0xffffffffu, rs0, 2);
    rs1 += __shfl_xor_sync(0xffffffffu, rs1, 1);
    rs1 += __shfl_xor_sync(0xffffffffu, rs1, 2);
    float i0 = 1.f / rs0, i1 = 1.f / rs1;

    size_t rbase = hb + (size_t)(m0 + wid * 16 + r) * DD;
#pragma unroll
    for (int j = 0; j < 8; j++) {
        float y00 = oacc[j][0] * i0, y01 = oacc[j][1] * i0;
        float y10 = oacc[j][2] * i1, y11 = oacc[j][3] * i1;
        __nv_bfloat162 h0 = __floats2bfloat162_rn(y00, y01);
        __nv_bfloat162 l0 = __floats2bfloat162_rn(y00 - __bfloat162float(h0.x),
                                                  y01 - __bfloat162float(h0.y));
        __nv_bfloat162 h1 = __floats2bfloat162_rn(y10, y11);
        __nv_bfloat162 l1 = __floats2bfloat162_rn(y10 - __bfloat162float(h1.x),
                                                  y11 - __bfloat162float(h1.y));
        *(uint32_t*)(ohi + rbase + j * 8 + c2)          = *(uint32_t*)&h0;
        *(uint32_t*)(olo + rbase + j * 8 + c2)          = *(uint32_t*)&l0;
        *(uint32_t*)(ohi + rbase + 8 * DD + j * 8 + c2) = *(uint32_t*)&h1;
        *(uint32_t*)(olo + rbase + 8 * DD + j * 8 + c2) = *(uint32_t*)&l1;
    }
}

// ------------------- host -------------------
extern "C" void kernel_launch(void* const* d_in, const int* in_sizes, int n_in,
                              void* d_out, int out_size) {
    const float* Q    = (const float*)d_in[0];
    const float* K    = (const float*)d_in[1];
    const float* V    = (const float*)d_in[2];
    const float* Wqk  = (const float*)d_in[3];
    const float* bqk  = (const float*)d_in[4];
    const float* Wv   = (const float*)d_in[5];
    const float* bv   = (const float*)d_in[6];
    const float* Wout = (const float*)d_in[7];
    const float* bout = (const float*)d_in[8];
    float* out = (float*)d_out;

    float *vf;
    __nv_bfloat16 *Qhi,*Qlo,*Khi,*Klo,*Vhi,*Vlo,*W1h,*W1l,*W2h,*W2l,*W3h,*W3l;
    __nv_bfloat16 *qhi,*qlo,*khi,*klo,*vth,*vtl,*ohi,*olo;
    cudaGetSymbolAddress((void**)&vf, g_vf);
    cudaGetSymbolAddress((void**)&Qhi, g_Qhi); cudaGetSymbolAddress((void**)&Qlo, g_Qlo);
    cudaGetSymbolAddress((void**)&Khi, g_Khi); cudaGetSymbolAddress((void**)&Klo, g_Klo);
    cudaGetSymbolAddress((void**)&Vhi, g_Vhi); cudaGetSymbolAddress((void**)&Vlo, g_Vlo);
    cudaGetSymbolAddress((void**)&W1h, g_W1hi); cudaGetSymbolAddress((void**)&W1l, g_W1lo);
    cudaGetSymbolAddress((void**)&W2h, g_W2hi); cudaGetSymbolAddress((void**)&W2l, g_W2lo);
    cudaGetSymbolAddress((void**)&W3h, g_W3hi); cudaGetSymbolAddress((void**)&W3l, g_W3lo);
    cudaGetSymbolAddress((void**)&qhi, g_qhi); cudaGetSymbolAddress((void**)&qlo, g_qlo);
    cudaGetSymbolAddress((void**)&khi, g_khi); cudaGetSymbolAddress((void**)&klo, g_klo);
    cudaGetSymbolAddress((void**)&vth, g_vthi); cudaGetSymbolAddress((void**)&vtl, g_vtlo);
    cudaGetSymbolAddress((void**)&ohi, g_ohi); cudaGetSymbolAddress((void**)&olo, g_olo);

    cudaFuncSetAttribute(gemm_mma, cudaFuncAttributeMaxDynamicSharedMemorySize, G_SMEM);
    cudaFuncSetAttribute(attn_mma, cudaFuncAttributeMaxDynamicSharedMemorySize, A_SMEM);

    const int TB = 256;
    split4x3<<<dim3(TOT/4/TB, 3), TB>>>((const float4*)Q, (uint2*)Qhi, (uint2*)Qlo,
                                        (const float4*)K, (uint2*)Khi, (uint2*)Klo,
                                        (const float4*)V, (uint2*)Vhi, (uint2*)Vlo);
    split4x3<<<dim3(EE*EE/4/TB, 3), TB>>>((const float4*)Wqk,  (uint2*)W1h, (uint2*)W1l,
                                          (const float4*)Wv,   (uint2*)W2h, (uint2*)W2l,
                                          (const float4*)Wout, (uint2*)W3h, (uint2*)W3l);

    // fused Q/K/V projection GEMMs (z = 0,1,2)
    const float QSC = 0.125f * 1.4426950408889634f;  // fold 1/sqrt(D) * log2(e)
    GemmArgs gp = {};
    gp.Ah[0]=Qhi; gp.Al[0]=Qlo; gp.Wh[0]=W1h; gp.Wl[0]=W1l; gp.bias[0]=bqk;
    gp.C[0]=nullptr; gp.Ch[0]=qhi; gp.Cl[0]=qlo; gp.scale[0]=QSC;
    gp.Ah[1]=Khi; gp.Al[1]=Klo; gp.Wh[1]=W1h; gp.Wl[1]=W1l; gp.bias[1]=bqk;
    gp.C[1]=nullptr; gp.Ch[1]=khi; gp.Cl[1]=klo; gp.scale[1]=1.f;
    gp.Ah[2]=Vhi; gp.Al[2]=Vlo; gp.Wh[2]=W2h; gp.Wl[2]=W2l; gp.bias[2]=bv;
    gp.C[2]=vf; gp.Ch[2]=nullptr; gp.Cl[2]=nullptr; gp.scale[2]=1.f;
    gemm_mma<<<dim3(EE/128, SQ/128, 3), TB, G_SMEM>>>(gp);

    vtrans_split<<<dim3(SQ/32, DD/32, HH), dim3(32,32)>>>(vf, vth, vtl);

    attn_mma<<<dim3(SQ/128, HH), TB, A_SMEM>>>(qhi, qlo, khi, klo, vth, vtl, ohi, olo);

    // out projection
    GemmArgs go = {};
    go.Ah[0]=ohi; go.Al[0]=olo; go.Wh[0]=W3h; go.Wl[0]=W3l; go.bias[0]=bout;
    go.C[0]=out; go.Ch[0]=nullptr; go.Cl[0]=nullptr; go.scale[0]=1.f;
    gemm_mma<<<dim3(EE/128, SQ/128, 1), TB, G_SMEM>>>(go);
}

// round 8
// speedup vs baseline: 1.0068x; 1.0068x over previous
#include <cuda_runtime.h>
#include <cuda_bf16.h>
#include <cstdint>

#define SQ 4096
#define EE 512
#define HH 8
#define DD 64
#define HSZ (SQ*DD)
#define TOT (SQ*EE)

// ------------------- global scratch -------------------
__device__ float g_vf[TOT];
__device__ __nv_bfloat16 g_Qhi[TOT], g_Qlo[TOT], g_Khi[TOT], g_Klo[TOT], g_Vhi[TOT], g_Vlo[TOT];
__device__ __nv_bfloat16 g_W1hi[EE*EE], g_W1lo[EE*EE];
__device__ __nv_bfloat16 g_W2hi[EE*EE], g_W2lo[EE*EE];
__device__ __nv_bfloat16 g_W3hi[EE*EE], g_W3lo[EE*EE];
__device__ __nv_bfloat16 g_qhi[TOT], g_qlo[TOT], g_khi[TOT], g_klo[TOT];
__device__ __nv_bfloat16 g_vthi[TOT], g_vtlo[TOT], g_ohi[TOT], g_olo[TOT];

// ------------------- helpers -------------------
__device__ __forceinline__ uint32_t smem_u32(const void* p) {
    uint32_t a;
    asm("{ .reg .u64 t; cvta.to.shared.u64 t, %1; cvt.u32.u64 %0, t; }" : "=r"(a) : "l"(p));
    return a;
}
#define LDSM4(R0,R1,R2,R3,ADDR) \
    asm volatile("ldmatrix.sync.aligned.m8n8.x4.shared.b16 {%0,%1,%2,%3}, [%4];" \
        : "=r"(R0),"=r"(R1),"=r"(R2),"=r"(R3) : "r"(ADDR))
#define MMA16816(C,A,B) \
    asm volatile("mma.sync.aligned.m16n8k16.row.col.f32.bf16.bf16.f32 " \
        "{%0,%1,%2,%3},{%4,%5,%6,%7},{%8,%9},{%0,%1,%2,%3};" \
        : "+f"((C)[0]),"+f"((C)[1]),"+f"((C)[2]),"+f"((C)[3]) \
        : "r"((A)[0]),"r"((A)[1]),"r"((A)[2]),"r"((A)[3]),"r"((B)[0]),"r"((B)[1]))
#define CPA16(DST,SRC) \
    asm volatile("cp.async.cg.shared.global [%0], [%1], 16;" :: "r"(DST), "l"(SRC) : "memory")
#define CPC() asm volatile("cp.async.commit_group;" ::: "memory")
#define CPW(N) asm volatile("cp.async.wait_group %0;" :: "n"(N) : "memory")
#define EX2(D,S) asm("ex2.approx.f32 %0, %1;" : "=f"(D) : "f"(S))

// ------------------- elementwise hi/lo split (3 tensors per launch) ----------
__global__ void split4x3(const float4* __restrict__ x0, uint2* __restrict__ h0, uint2* __restrict__ l0,
                         const float4* __restrict__ x1, uint2* __restrict__ h1, uint2* __restrict__ l1,
                         const float4* __restrict__ x2, uint2* __restrict__ h2, uint2* __restrict__ l2) {
    const float4* x = blockIdx.y == 0 ? x0 : blockIdx.y == 1 ? x1 : x2;
    uint2* hi = blockIdx.y == 0 ? h0 : blockIdx.y == 1 ? h1 : h2;
    uint2* lo = blockIdx.y == 0 ? l0 : blockIdx.y == 1 ? l1 : l2;
    int i = blockIdx.x * blockDim.x + threadIdx.x;
    float4 v = x[i];
    __nv_bfloat162 a01 = __floats2bfloat162_rn(v.x, v.y);
    __nv_bfloat162 a23 = __floats2bfloat162_rn(v.z, v.w);
    __nv_bfloat162 b01 = __floats2bfloat162_rn(v.x - __bfloat162float(a01.x),
                                               v.y - __bfloat162float(a01.y));
    __nv_bfloat162 b23 = __floats2bfloat162_rn(v.z - __bfloat162float(a23.x),
                                               v.w - __bfloat162float(a23.y));
    uint2 hv, lv;
    hv.x = *(uint32_t*)&a01; hv.y = *(uint32_t*)&a23;
    lv.x = *(uint32_t*)&b01; lv.y = *(uint32_t*)&b23;
    hi[i] = hv; lo[i] = lv;
}

// per-head transpose of V: [h][4096][64] -> [h][64][4096], split hi/lo
__global__ void vtrans_split(const float* __restrict__ vf,
                             __nv_bfloat16* __restrict__ vthi,
                             __nv_bfloat16* __restrict__ vtlo) {
    __shared__ float tile[32][33];
    int h = blockIdx.z, t0 = blockIdx.x * 32, d0 = blockIdx.y * 32;
    int tx = threadIdx.x, ty = threadIdx.y;
    tile[ty][tx] = vf[(size_t)h * HSZ + (size_t)(t0 + ty) * DD + d0 + tx];
    __syncthreads();
    float v = tile[tx][ty];
    __nv_bfloat16 hh = __float2bfloat16(v);
    __nv_bfloat16 ll = __float2bfloat16(v - __bfloat162float(hh));
    size_t o = (size_t)h * HSZ + (size_t)(d0 + ty) * SQ + t0 + tx;
    vthi[o] = hh; vtlo[o] = ll;
}

// ------------------- fused mma.sync GEMM (K-chunk 16, 3-stage, 2 CTA/SM) -----
#define GP16 48
#define GMSZ (128*GP16)
#define GSTG (4*GMSZ)
#define G_SMEM (3*GSTG)

struct GemmArgs {
    const __nv_bfloat16 *Ah[3], *Al[3], *Wh[3], *Wl[3];
    const float* bias[3];
    float* C[3];
    __nv_bfloat16 *Ch[3], *Cl[3];
    float scale[3];
};

__device__ __forceinline__ void gemm_prefetch16(
    uint32_t sbs, int tid, int m0, int n0, int ch,
    const __nv_bfloat16* Ah, const __nv_bfloat16* Al,
    const __nv_bfloat16* Wh, const __nv_bfloat16* Wl)
{
#pragma unroll
    for (int q = 0; q < 4; q++) {
        int id = q * 256 + tid;
        int mat = id >> 8, rem = id & 255, row = rem >> 1, col = rem & 1;
        const __nv_bfloat16* g =
            (mat == 0 ? Ah : mat == 1 ? Al : mat == 2 ? Wh : Wl)
            + (size_t)((mat < 2 ? m0 : n0) + row) * EE + ch * 16 + col * 8;
        CPA16(sbs + mat * GMSZ + row * GP16 + col * 16, g);
    }
}

__global__ void __launch_bounds__(256, 2) gemm_mma(GemmArgs ga)
{
    extern __shared__ char sm[];
    uint32_t sb = smem_u32(sm);
    int tid = threadIdx.x, wid = tid >> 5, lane = tid & 31;
    int wm = wid & 3, wn = wid >> 2;
    int m0 = blockIdx.y * 128, n0 = blockIdx.x * 128;
    int z = blockIdx.z;
    int l15 = lane & 15, lh = lane >> 4;

    const __nv_bfloat16 *Ah = ga.Ah[z], *Al = ga.Al[z], *Wh = ga.Wh[z], *Wl = ga.Wl[z];
    const float* bias = ga.bias[z];
    float* C = ga.C[z];
    __nv_bfloat16 *Chi = ga.Ch[z], *Clo = ga.Cl[z];
    float scale = ga.scale[z];

    float acc[2][8][4] = {};

    gemm_prefetch16(sb, tid, m0, n0, 0, Ah, Al, Wh, Wl); CPC();
    gemm_prefetch16(sb + GSTG, tid, m0, n0, 1, Ah, Al, Wh, Wl); CPC();

    for (int ch = 0; ch < 32; ch++) {
        if (ch == 31) { CPW(0); } else { CPW(1); }
        __syncthreads();
        if (ch + 2 < 32) {
            gemm_prefetch16(sb + ((ch + 2) % 3) * GSTG, tid, m0, n0, ch + 2, Ah, Al, Wh, Wl);
            CPC();
        }
        uint32_t sbs = sb + (ch % 3) * GSTG;

        uint32_t ah[2][4], al[2][4];
#pragma unroll
        for (int mt = 0; mt < 2; mt++) {
            uint32_t addr = sbs + (wm * 32 + mt * 16 + l15) * GP16 + lh * 16;
            LDSM4(ah[mt][0], ah[mt][1], ah[mt][2], ah[mt][3], addr);
            LDSM4(al[mt][0], al[mt][1], al[mt][2], al[mt][3], addr + GMSZ);
        }
#pragma unroll
        for (int jt = 0; jt < 4; jt++) {
            uint32_t addr = sbs + 2 * GMSZ + (wn * 64 + jt * 16 + l15) * GP16 + lh * 16;
            uint32_t h0, h1, h2, h3, l0, l1, l2, l3;
            LDSM4(h0, h1, h2, h3, addr);
            LDSM4(l0, l1, l2, l3, addr + GMSZ);
            uint32_t b0[2] = {h0, h2}, b1[2] = {h1, h3};
            uint32_t c0[2] = {l0, l2}, c1[2] = {l1, l3};
#pragma unroll
            for (int mt = 0; mt < 2; mt++) {
                MMA16816(acc[mt][2*jt],   ah[mt], b0);
                MMA16816(acc[mt][2*jt],   al[mt], b0);
                MMA16816(acc[mt][2*jt],   ah[mt], c0);
                MMA16816(acc[mt][2*jt+1], ah[mt], b1);
                MMA16816(acc[mt][2*jt+1], al[mt], b1);
                MMA16816(acc[mt][2*jt+1], ah[mt], c1);
            }
        }
    }

    int r = lane >> 2, c2 = (lane & 3) * 2;
#pragma unroll
    for (int mt = 0; mt < 2; mt++) {
        size_t rbase = (size_t)(m0 + wm * 32 + mt * 16 + r) * EE + n0 + wn * 64;
#pragma unroll
        for (int j = 0; j < 8; j++) {
            float b0 = __ldg(bias + n0 + wn * 64 + j * 8 + c2);
            float b1 = __ldg(bias + n0 + wn * 64 + j * 8 + c2 + 1);
            float y00 = (acc[mt][j][0] + b0) * scale, y01 = (acc[mt][j][1] + b1) * scale;
            float y10 = (acc[mt][j][2] + b0) * scale, y11 = (acc[mt][j][3] + b1) * scale;
            if (Chi) {
                __nv_bfloat162 h0 = __floats2bfloat162_rn(y00, y01);
                __nv_bfloat162 l0 = __floats2bfloat162_rn(y00 - __bfloat162float(h0.x),
                                                          y01 - __bfloat162float(h0.y));
                __nv_bfloat162 h1 = __floats2bfloat162_rn(y10, y11);
                __nv_bfloat162 l1 = __floats2bfloat162_rn(y10 - __bfloat162float(h1.x),
                                                          y11 - __bfloat162float(h1.y));
                *(uint32_t*)(Chi + rbase + j * 8 + c2)          = *(uint32_t*)&h0;
                *(uint32_t*)(Clo + rbase + j * 8 + c2)          = *(uint32_t*)&l0;
                *(uint32_t*)(Chi + rbase + 8 * EE + j * 8 + c2) = *(uint32_t*)&h1;
                *(uint32_t*)(Clo + rbase + 8 * EE + j * 8 + c2) = *(uint32_t*)&l1;
            } else {
                *(float2*)(C + rbase + j * 8 + c2)          = make_float2(y00, y01);
                *(float2*)(C + rbase + 8 * EE + j * 8 + c2) = make_float2(y10, y11);
            }
        }
    }
}

// ------------------- mma.sync flash attention (slab-interleaved) -------------
#define APITCH 72
#define AMSZ (64*APITCH*2)
#define ASTG (4*AMSZ)
#define A_SMEM (3*ASTG)

__device__ __forceinline__ void attn_prefetch(
    uint32_t sbs, int tid, size_t hb, int t0,
    const __nv_bfloat16* khi, const __nv_bfloat16* klo,
    const __nv_bfloat16* vth, const __nv_bfloat16* vtl)
{
#pragma unroll
    for (int q = 0; q < 8; q++) {
        int id = q * 256 + tid;
        int mat = id >> 9, rem = id & 511, row = rem >> 3, col = rem & 7;
        const __nv_bfloat16* g;
        if (mat == 0)      g = khi + hb + (size_t)(t0 + row) * DD + col * 8;
        else if (mat == 1) g = klo + hb + (size_t)(t0 + row) * DD + col * 8;
        else if (mat == 2) g = vth + hb + (size_t)row * SQ + t0 + col * 8;
        else               g = vtl + hb + (size_t)row * SQ + t0 + col * 8;
        CPA16(sbs + mat * AMSZ + row * (APITCH * 2) + col * 16, g);
    }
}

__global__ void __launch_bounds__(256, 2) attn_mma(
    const __nv_bfloat16* __restrict__ qhi, const __nv_bfloat16* __restrict__ qlo,
    const __nv_bfloat16* __restrict__ khi, const __nv_bfloat16* __restrict__ klo,
    const __nv_bfloat16* __restrict__ vth, const __nv_bfloat16* __restrict__ vtl,
    __nv_bfloat16* __restrict__ ohi, __nv_bfloat16* __restrict__ olo)
{
    extern __shared__ char sm[];
    uint32_t sb = smem_u32(sm);
    int tid = threadIdx.x, wid = tid >> 5, lane = tid & 31;
    int head = blockIdx.y, m0 = blockIdx.x * 128;
    const size_t hb = (size_t)head * HSZ;
    int r = lane >> 2, c2 = (lane & 3) * 2;
    int l15 = lane & 15, lh = lane >> 4;

    attn_prefetch(sb, tid, hb, 0, khi, klo, vth, vtl); CPC();
    attn_prefetch(sb + ASTG, tid, hb, 64, khi, klo, vth, vtl); CPC();

    // Q fragments (hi/lo); q pre-scaled by 0.125*log2e in the projection
    uint32_t qh[4][4], ql[4][4];
    {
        const __nv_bfloat16* q0h = qhi + hb + (size_t)(m0 + wid * 16) * DD;
        const __nv_bfloat16* q0l = qlo + hb + (size_t)(m0 + wid * 16) * DD;
#pragma unroll
        for (int ks = 0; ks < 4; ks++)
#pragma unroll
            for (int j = 0; j < 4; j++) {
                int rr = r + (j & 1) * 8;
                int kk = ks * 16 + c2 + (j >> 1) * 8;
                qh[ks][j] = *(const uint32_t*)(q0h + rr * DD + kk);
                ql[ks][j] = *(const uint32_t*)(q0l + rr * DD + kk);
            }
    }

    float oacc[8][4] = {};
    float rs0 = 0.f, rs1 = 0.f;

    for (int t = 0; t < 64; t++) {
        if (t == 63) { CPW(0); } else { CPW(1); }
        __syncthreads();
        if (t + 2 < 64) {
            attn_prefetch(sb + ((t + 2) % 3) * ASTG, tid, hb, (t + 2) * 64, khi, klo, vth, vtl);
            CPC();
        }
        uint32_t sbs = sb + (t % 3) * ASTG;

        // per 16-kv slab: S(slab) -> exp/pack -> PV(slab). sacc live = 8 regs.
#pragma unroll
        for (int tt = 0; tt < 4; tt++) {
            float s0[4] = {}, s1[4] = {};
#pragma unroll
            for (int ks = 0; ks < 4; ks++) {
                uint32_t addr = sbs + (tt * 16 + l15) * (APITCH * 2) + (ks * 16 + 8 * lh) * 2;
                uint32_t h0, h1, h2, h3, l0, l1, l2, l3;
                LDSM4(h0, h1, h2, h3, addr);
                LDSM4(l0, l1, l2, l3, addr + AMSZ);
                uint32_t b0[2] = {h0, h2}, b1[2] = {h1, h3};
                uint32_t c0[2] = {l0, l2}, c1[2] = {l1, l3};
                MMA16816(s0, qh[ks], b0);
                MMA16816(s0, ql[ks], b0);
                MMA16816(s0, qh[ks], c0);
                MMA16816(s1, qh[ks], b1);
                MMA16816(s1, ql[ks], b1);
                MMA16816(s1, qh[ks], c1);
            }

            float e0[4], e1[4];
#pragma unroll
            for (int e = 0; e < 4; e++) { EX2(e0[e], s0[e]); EX2(e1[e], s1[e]); }
            rs0 += e0[0] + e0[1] + e1[0] + e1[1];
            rs1 += e0[2] + e0[3] + e1[2] + e1[3];
            uint32_t pa[4], pl[4];
            {
                __nv_bfloat162 h, l;
                h = __floats2bfloat162_rn(e0[0], e0[1]);
                l = __floats2bfloat162_rn(e0[0] - __bfloat162float(h.x), e0[1] - __bfloat162float(h.y));
                pa[0] = *(uint32_t*)&h; pl[0] = *(uint32_t*)&l;
                h = __floats2bfloat162_rn(e0[2], e0[3]);
                l = __floats2bfloat162_rn(e0[2] - __bfloat162float(h.x), e0[3] - __bfloat162float(h.y));
                pa[1] = *(uint32_t*)&h; pl[1] = *(uint32_t*)&l;
                h = __floats2bfloat162_rn(e1[0], e1[1]);
                l = __floats2bfloat162_rn(e1[0] - __bfloat162float(h.x), e1[1] - __bfloat162float(h.y));
                pa[2] = *(uint32_t*)&h; pl[2] = *(uint32_t*)&l;
                h = __floats2bfloat162_rn(e1[2], e1[3]);
                l = __floats2bfloat162_rn(e1[2] - __bfloat162float(h.x), e1[3] - __bfloat162float(h.y));
                pa[3] = *(uint32_t*)&h; pl[3] = *(uint32_t*)&l;
            }
#pragma unroll
            for (int jt = 0; jt < 4; jt++) {
                uint32_t addr = sbs + 2 * AMSZ + (jt * 16 + l15) * (APITCH * 2)
                              + (tt * 16 + 8 * lh) * 2;
                uint32_t h0, h1, h2, h3, l0, l1, l2, l3;
                LDSM4(h0, h1, h2, h3, addr);
                LDSM4(l0, l1, l2, l3, addr + AMSZ);
                uint32_t b0[2] = {h0, h2}, b1[2] = {h1, h3};
                uint32_t c0[2] = {l0, l2}, c1[2] = {l1, l3};
                MMA16816(oacc[2*jt],   pa, b0);
                MMA16816(oacc[2*jt],   pl, b0);
                MMA16816(oacc[2*jt],   pa, c0);
                MMA16816(oacc[2*jt+1], pa, b1);
                MMA16816(oacc[2*jt+1], pl, b1);
                MMA16816(oacc[2*jt+1], pa, c1);
            }
        }
    }

    // rowsum reduce across the quad
    rs0 += __shfl_xor_sync(0xffffffffu, rs0, 1);
    rs0 += __shfl_xor_sync(0xffffffffu, rs0, 2);
    rs1 += __shfl_xor_sync(0xffffffffu, rs1, 1);
    rs1 += __shfl_xor_sync(0xffffffffu, rs1, 2);
    float i0 = 1.f / rs0, i1 = 1.f / rs1;

    size_t rbase = hb + (size_t)(m0 + wid * 16 + r) * DD;
#pragma unroll
    for (int j = 0; j < 8; j++) {
        float y00 = oacc[j][0] * i0, y01 = oacc[j][1] * i0;
        float y10 = oacc[j][2] * i1, y11 = oacc[j][3] * i1;
        __nv_bfloat162 h0 = __floats2bfloat162_rn(y00, y01);
        __nv_bfloat162 l0 = __floats2bfloat162_rn(y00 - __bfloat162float(h0.x),
                                                  y01 - __bfloat162float(h0.y));
        __nv_bfloat162 h1 = __floats2bfloat162_rn(y10, y11);
        __nv_bfloat162 l1 = __floats2bfloat162_rn(y10 - __bfloat162float(h1.x),
                                                  y11 - __bfloat162float(h1.y));
        *(uint32_t*)(ohi + rbase + j * 8 + c2)          = *(uint32_t*)&h0;
        *(uint32_t*)(olo + rbase + j * 8 + c2)          = *(uint32_t*)&l0;
        *(uint32_t*)(ohi + rbase + 8 * DD + j * 8 + c2) = *(uint32_t*)&h1;
        *(uint32_t*)(olo + rbase + 8 * DD + j * 8 + c2) = *(uint32_t*)&l1;
    }
}

// ------------------- host -------------------
extern "C" void kernel_launch(void* const* d_in, const int* in_sizes, int n_in,
                              void* d_out, int out_size) {
    const float* Q    = (const float*)d_in[0];
    const float* K    = (const float*)d_in[1];
    const float* V    = (const float*)d_in[2];
    const float* Wqk  = (const float*)d_in[3];
    const float* bqk  = (const float*)d_in[4];
    const float* Wv   = (const float*)d_in[5];
    const float* bv   = (const float*)d_in[6];
    const float* Wout = (const float*)d_in[7];
    const float* bout = (const float*)d_in[8];
    float* out = (float*)d_out;

    float *vf;
    __nv_bfloat16 *Qhi,*Qlo,*Khi,*Klo,*Vhi,*Vlo,*W1h,*W1l,*W2h,*W2l,*W3h,*W3l;
    __nv_bfloat16 *qhi,*qlo,*khi,*klo,*vth,*vtl,*ohi,*olo;
    cudaGetSymbolAddress((void**)&vf, g_vf);
    cudaGetSymbolAddress((void**)&Qhi, g_Qhi); cudaGetSymbolAddress((void**)&Qlo, g_Qlo);
    cudaGetSymbolAddress((void**)&Khi, g_Khi); cudaGetSymbolAddress((void**)&Klo, g_Klo);
    cudaGetSymbolAddress((void**)&Vhi, g_Vhi); cudaGetSymbolAddress((void**)&Vlo, g_Vlo);
    cudaGetSymbolAddress((void**)&W1h, g_W1hi); cudaGetSymbolAddress((void**)&W1l, g_W1lo);
    cudaGetSymbolAddress((void**)&W2h, g_W2hi); cudaGetSymbolAddress((void**)&W2l, g_W2lo);
    cudaGetSymbolAddress((void**)&W3h, g_W3hi); cudaGetSymbolAddress((void**)&W3l, g_W3lo);
    cudaGetSymbolAddress((void**)&qhi, g_qhi); cudaGetSymbolAddress((void**)&qlo, g_qlo);
    cudaGetSymbolAddress((void**)&khi, g_khi); cudaGetSymbolAddress((void**)&klo, g_klo);
    cudaGetSymbolAddress((void**)&vth, g_vthi); cudaGetSymbolAddress((void**)&vtl, g_vtlo);
    cudaGetSymbolAddress((void**)&ohi, g_ohi); cudaGetSymbolAddress((void**)&olo, g_olo);

    cudaFuncSetAttribute(gemm_mma, cudaFuncAttributeMaxDynamicSharedMemorySize, G_SMEM);
    cudaFuncSetAttribute(attn_mma, cudaFuncAttributeMaxDynamicSharedMemorySize, A_SMEM);

    const int TB = 256;
    split4x3<<<dim3(TOT/4/TB, 3), TB>>>((const float4*)Q, (uint2*)Qhi, (uint2*)Qlo,
                                        (const float4*)K, (uint2*)Khi, (uint2*)Klo,
                                        (const float4*)V, (uint2*)Vhi, (uint2*)Vlo);
    split4x3<<<dim3(EE*EE/4/TB, 3), TB>>>((const float4*)Wqk,  (uint2*)W1h, (uint2*)W1l,
                                          (const float4*)Wv,   (uint2*)W2h, (uint2*)W2l,
                                          (const float4*)Wout, (uint2*)W3h, (uint2*)W3l);

    const float QSC = 0.125f * 1.4426950408889634f;
    GemmArgs gp = {};
    gp.Ah[0]=Qhi; gp.Al[0]=Qlo; gp.Wh[0]=W1h; gp.Wl[0]=W1l; gp.bias[0]=bqk;
    gp.C[0]=nullptr; gp.Ch[0]=qhi; gp.Cl[0]=qlo; gp.scale[0]=QSC;
    gp.Ah[1]=Khi; gp.Al[1]=Klo; gp.Wh[1]=W1h; gp.Wl[1]=W1l; gp.bias[1]=bqk;
    gp.C[1]=nullptr; gp.Ch[1]=khi; gp.Cl[1]=klo; gp.scale[1]=1.f;
    gp.Ah[2]=Vhi; gp.Al[2]=Vlo; gp.Wh[2]=W2h; gp.Wl[2]=W2l; gp.bias[2]=bv;
    gp.C[2]=vf; gp.Ch[2]=nullptr; gp.Cl[2]=nullptr; gp.scale[2]=1.f;
    gemm_mma<<<dim3(EE/128, SQ/128, 3), TB, G_SMEM>>>(gp);

    vtrans_split<<<dim3(SQ/32, DD/32, HH), dim3(32,32)>>>(vf, vth, vtl);

    attn_mma<<<dim3(SQ/128, HH), TB, A_SMEM>>>(qhi, qlo, khi, klo, vth, vtl, ohi, olo);

    GemmArgs go = {};
    go.Ah[0]=ohi; go.Al[0]=olo; go.Wh[0]=W3h; go.Wl[0]=W3l; go.bias[0]=bout;
    go.C[0]=out; go.Ch[0]=nullptr; go.Cl[0]=nullptr; go.scale[0]=1.f;
    gemm_mma<<<dim3(EE/128, SQ/128, 1), TB, G_SMEM>>>(go);
}

// round 10
// speedup vs baseline: 1.4417x; 1.4320x over previous
#include <cuda_runtime.h>
#include <cuda_fp16.h>
#include <cstdint>

#define SQ 4096
#define EE 512
#define HH 8
#define DD 64
#define HSZ (SQ*DD)
#define TOT (SQ*EE)

// ------------------- global scratch -------------------
__device__ float g_vf[TOT];
__device__ __half g_Qh[TOT], g_Ql[TOT], g_Kh[TOT], g_Kl[TOT], g_Vh[TOT], g_Vl[TOT];
__device__ __half g_W1h[EE*EE], g_W2h[EE*EE], g_W3h[EE*EE];
__device__ __half g_qh[TOT], g_ql[TOT], g_kh[TOT];
__device__ __half g_vth[TOT], g_vtl[TOT], g_oh[TOT], g_ol[TOT];

// ------------------- helpers -------------------
__device__ __forceinline__ uint32_t smem_u32(const void* p) {
    uint32_t a;
    asm("{ .reg .u64 t; cvta.to.shared.u64 t, %1; cvt.u32.u64 %0, t; }" : "=r"(a) : "l"(p));
    return a;
}
#define LDSM4(R0,R1,R2,R3,ADDR) \
    asm volatile("ldmatrix.sync.aligned.m8n8.x4.shared.b16 {%0,%1,%2,%3}, [%4];" \
        : "=r"(R0),"=r"(R1),"=r"(R2),"=r"(R3) : "r"(ADDR))
#define MMA16816(C,A,B) \
    asm volatile("mma.sync.aligned.m16n8k16.row.col.f32.f16.f16.f32 " \
        "{%0,%1,%2,%3},{%4,%5,%6,%7},{%8,%9},{%0,%1,%2,%3};" \
        : "+f"((C)[0]),"+f"((C)[1]),"+f"((C)[2]),"+f"((C)[3]) \
        : "r"((A)[0]),"r"((A)[1]),"r"((A)[2]),"r"((A)[3]),"r"((B)[0]),"r"((B)[1]))
#define CPA16(DST,SRC) \
    asm volatile("cp.async.cg.shared.global [%0], [%1], 16;" :: "r"(DST), "l"(SRC) : "memory")
#define CPC() asm volatile("cp.async.commit_group;" ::: "memory")
#define CPW(N) asm volatile("cp.async.wait_group %0;" :: "n"(N) : "memory")
#define EX2(D,S) asm("ex2.approx.f32 %0, %1;" : "=f"(D) : "f"(S))

// ------------------- elementwise splits -------------------
__global__ void split2x3(const float4* __restrict__ x0, uint2* __restrict__ h0, uint2* __restrict__ l0,
                         const float4* __restrict__ x1, uint2* __restrict__ h1, uint2* __restrict__ l1,
                         const float4* __restrict__ x2, uint2* __restrict__ h2, uint2* __restrict__ l2) {
    const float4* x = blockIdx.y == 0 ? x0 : blockIdx.y == 1 ? x1 : x2;
    uint2* hi = blockIdx.y == 0 ? h0 : blockIdx.y == 1 ? h1 : h2;
    uint2* lo = blockIdx.y == 0 ? l0 : blockIdx.y == 1 ? l1 : l2;
    int i = blockIdx.x * blockDim.x + threadIdx.x;
    float4 v = x[i];
    __half2 a01 = __floats2half2_rn(v.x, v.y);
    __half2 a23 = __floats2half2_rn(v.z, v.w);
    __half2 b01 = __floats2half2_rn(v.x - __half2float(a01.x), v.y - __half2float(a01.y));
    __half2 b23 = __floats2half2_rn(v.z - __half2float(a23.x), v.w - __half2float(a23.y));
    uint2 hv, lv;
    hv.x = *(uint32_t*)&a01; hv.y = *(uint32_t*)&a23;
    lv.x = *(uint32_t*)&b01; lv.y = *(uint32_t*)&b23;
    hi[i] = hv; lo[i] = lv;
}

__global__ void cvt1x3(const float4* __restrict__ x0, uint2* __restrict__ h0,
                       const float4* __restrict__ x1, uint2* __restrict__ h1,
                       const float4* __restrict__ x2, uint2* __restrict__ h2) {
    const float4* x = blockIdx.y == 0 ? x0 : blockIdx.y == 1 ? x1 : x2;
    uint2* hi = blockIdx.y == 0 ? h0 : blockIdx.y == 1 ? h1 : h2;
    int i = blockIdx.x * blockDim.x + threadIdx.x;
    float4 v = x[i];
    __half2 a01 = __floats2half2_rn(v.x, v.y);
    __half2 a23 = __floats2half2_rn(v.z, v.w);
    uint2 hv;
    hv.x = *(uint32_t*)&a01; hv.y = *(uint32_t*)&a23;
    hi[i] = hv;
}

// per-head transpose of V (flat per-head chop — layout-correct): hi/lo fp16 out
__global__ void vtrans_split(const float* __restrict__ vf,
                             __half* __restrict__ vthi, __half* __restrict__ vtlo) {
    __shared__ float tile[32][33];
    int h = blockIdx.z, t0 = blockIdx.x * 32, d0 = blockIdx.y * 32;
    int tx = threadIdx.x, ty = threadIdx.y;
    tile[ty][tx] = vf[(size_t)h * HSZ + (size_t)(t0 + ty) * DD + d0 + tx];
    __syncthreads();
    float v = tile[tx][ty];
    __half hh = __float2half_rn(v);
    __half ll = __float2half_rn(v - __half2float(hh));
    size_t o = (size_t)h * HSZ + (size_t)(d0 + ty) * SQ + t0 + tx;
    vthi[o] = hh; vtlo[o] = ll;
}

// ------------------- fused fp16 2-term GEMM (K-chunk 16, 4-stage) -----------
#define GP16 48
#define GMSZ (128*GP16)
#define GSTG (3*GMSZ)
#define G_SMEM (4*GSTG)                  // 73728 B

struct GemmArgs {
    const __half *Ah[3], *Al[3], *Wh[3];
    const float* bias[3];
    float* Cf[3];
    __half *Ch[3], *Cl[3];
    float scale[3];
    int mode[3];   // 0: fp32 out, 1: 2-term fp16, 2: single fp16
};

__device__ __forceinline__ void gemm_pf(
    uint32_t sbs, int tid, int m0, int n0, int ch,
    const __half* Ah, const __half* Al, const __half* Wh)
{
#pragma unroll
    for (int q = 0; q < 3; q++) {
        int id = q * 256 + tid;
        int mat = id >> 8, rem = id & 255, row = rem >> 1, col = rem & 1;
        const __half* g = (mat == 0 ? Ah : mat == 1 ? Al : Wh)
            + (size_t)((mat < 2 ? m0 : n0) + row) * EE + ch * 16 + col * 8;
        CPA16(sbs + mat * GMSZ + row * GP16 + col * 16, g);
    }
}

__global__ void __launch_bounds__(256, 2) gemm_mma(GemmArgs ga)
{
    extern __shared__ char sm[];
    uint32_t sb = smem_u32(sm);
    int tid = threadIdx.x, wid = tid >> 5, lane = tid & 31;
    int wm = wid & 3, wn = wid >> 2;
    int m0 = blockIdx.y * 128, n0 = blockIdx.x * 128;
    int z = blockIdx.z;
    int l15 = lane & 15, lh = lane >> 4;

    const __half *Ah = ga.Ah[z], *Al = ga.Al[z], *Wh = ga.Wh[z];
    const float* bias = ga.bias[z];
    float* Cf = ga.Cf[z];
    __half *Chi = ga.Ch[z], *Clo = ga.Cl[z];
    float scale = ga.scale[z];
    int mode = ga.mode[z];

    float acc[2][8][4] = {};

    gemm_pf(sb,            tid, m0, n0, 0, Ah, Al, Wh); CPC();
    gemm_pf(sb + GSTG,     tid, m0, n0, 1, Ah, Al, Wh); CPC();
    gemm_pf(sb + 2 * GSTG, tid, m0, n0, 2, Ah, Al, Wh); CPC();

    for (int ch = 0; ch < 32; ch++) {
        __syncthreads();
        if (ch + 3 < 32) {
            gemm_pf(sb + ((ch + 3) & 3) * GSTG, tid, m0, n0, ch + 3, Ah, Al, Wh);
            CPC();
            CPW(3);
        } else {
            CPW(0);
        }
        uint32_t sbs = sb + (ch & 3) * GSTG;

        uint32_t ah[2][4], al[2][4];
#pragma unroll
        for (int mt = 0; mt < 2; mt++) {
            uint32_t addr = sbs + (wm * 32 + mt * 16 + l15) * GP16 + lh * 16;
            LDSM4(ah[mt][0], ah[mt][1], ah[mt][2], ah[mt][3], addr);
            LDSM4(al[mt][0], al[mt][1], al[mt][2], al[mt][3], addr + GMSZ);
        }
#pragma unroll
        for (int jt = 0; jt < 4; jt++) {
            uint32_t addr = sbs + 2 * GMSZ + (wn * 64 + jt * 16 + l15) * GP16 + lh * 16;
            uint32_t h0, h1, h2, h3;
            LDSM4(h0, h1, h2, h3, addr);
            uint32_t b0[2] = {h0, h2}, b1[2] = {h1, h3};
#pragma unroll
            for (int mt = 0; mt < 2; mt++) {
                MMA16816(acc[mt][2*jt],   ah[mt], b0);
                MMA16816(acc[mt][2*jt],   al[mt], b0);
                MMA16816(acc[mt][2*jt+1], ah[mt], b1);
                MMA16816(acc[mt][2*jt+1], al[mt], b1);
            }
        }
    }

    int r = lane >> 2, c2 = (lane & 3) * 2;
#pragma unroll
    for (int mt = 0; mt < 2; mt++) {
        size_t rbase = (size_t)(m0 + wm * 32 + mt * 16 + r) * EE + n0 + wn * 64;
#pragma unroll
        for (int j = 0; j < 8; j++) {
            float b0 = __ldg(bias + n0 + wn * 64 + j * 8 + c2);
            float b1 = __ldg(bias + n0 + wn * 64 + j * 8 + c2 + 1);
            float y00 = (acc[mt][j][0] + b0) * scale, y01 = (acc[mt][j][1] + b1) * scale;
            float y10 = (acc[mt][j][2] + b0) * scale, y11 = (acc[mt][j][3] + b1) * scale;
            if (mode == 0) {
                *(float2*)(Cf + rbase + j * 8 + c2)          = make_float2(y00, y01);
                *(float2*)(Cf + rbase + 8 * EE + j * 8 + c2) = make_float2(y10, y11);
            } else if (mode == 2) {
                __half2 p0 = __floats2half2_rn(y00, y01);
                __half2 p1 = __floats2half2_rn(y10, y11);
                *(uint32_t*)(Chi + rbase + j * 8 + c2)          = *(uint32_t*)&p0;
                *(uint32_t*)(Chi + rbase + 8 * EE + j * 8 + c2) = *(uint32_t*)&p1;
            } else {
                __half2 p0 = __floats2half2_rn(y00, y01);
                __half2 q0 = __floats2half2_rn(y00 - __half2float(p0.x), y01 - __half2float(p0.y));
                __half2 p1 = __floats2half2_rn(y10, y11);
                __half2 q1 = __floats2half2_rn(y10 - __half2float(p1.x), y11 - __half2float(p1.y));
                *(uint32_t*)(Chi + rbase + j * 8 + c2)          = *(uint32_t*)&p0;
                *(uint32_t*)(Clo + rbase + j * 8 + c2)          = *(uint32_t*)&q0;
                *(uint32_t*)(Chi + rbase + 8 * EE + j * 8 + c2) = *(uint32_t*)&p1;
                *(uint32_t*)(Clo + rbase + 8 * EE + j * 8 + c2) = *(uint32_t*)&q1;
            }
        }
    }
}

// ------------------- fp16 2-term flash attention (4-stage) -------------------
#define AP16 144
#define AMSZ (64*AP16)
#define ASTG (3*AMSZ)                    // Kh, Vth, Vtl
#define A_SMEM (4*ASTG)                  // 110592 B

__device__ __forceinline__ void attn_pf(
    uint32_t sbs, int tid, size_t hb, int t0,
    const __half* kh, const __half* vth, const __half* vtl)
{
#pragma unroll
    for (int q = 0; q < 6; q++) {
        int id = q * 256 + tid;
        int mat = id >> 9, rem = id & 511, row = rem >> 3, col = rem & 7;
        const __half* g;
        if (mat == 0)      g = kh  + hb + (size_t)(t0 + row) * DD + col * 8;
        else if (mat == 1) g = vth + hb + (size_t)row * SQ + t0 + col * 8;
        else               g = vtl + hb + (size_t)row * SQ + t0 + col * 8;
        CPA16(sbs + mat * AMSZ + row * AP16 + col * 16, g);
    }
}

__global__ void __launch_bounds__(256, 2) attn_mma(
    const __half* __restrict__ qh_g, const __half* __restrict__ ql_g,
    const __half* __restrict__ kh_g,
    const __half* __restrict__ vth, const __half* __restrict__ vtl,
    __half* __restrict__ oh_g, __half* __restrict__ ol_g)
{
    extern __shared__ char sm[];
    uint32_t sb = smem_u32(sm);
    int tid = threadIdx.x, wid = tid >> 5, lane = tid & 31;
    int head = blockIdx.y, m0 = blockIdx.x * 128;
    const size_t hb = (size_t)head * HSZ;
    int r = lane >> 2, c2 = (lane & 3) * 2;
    int l15 = lane & 15, lh = lane >> 4;

    attn_pf(sb,            tid, hb, 0,   kh_g, vth, vtl); CPC();
    attn_pf(sb + ASTG,     tid, hb, 64,  kh_g, vth, vtl); CPC();
    attn_pf(sb + 2 * ASTG, tid, hb, 128, kh_g, vth, vtl); CPC();

    // Q fragments (hi/lo fp16); q pre-scaled by 0.125*log2e
    uint32_t qh[4][4], ql[4][4];
    {
        const __half* q0h = qh_g + hb + (size_t)(m0 + wid * 16) * DD;
        const __half* q0l = ql_g + hb + (size_t)(m0 + wid * 16) * DD;
#pragma unroll
        for (int ks = 0; ks < 4; ks++)
#pragma unroll
            for (int j = 0; j < 4; j++) {
                int rr = r + (j & 1) * 8;
                int kk = ks * 16 + c2 + (j >> 1) * 8;
                qh[ks][j] = *(const uint32_t*)(q0h + rr * DD + kk);
                ql[ks][j] = *(const uint32_t*)(q0l + rr * DD + kk);
            }
    }

    float oacc[8][4] = {};
    float rs0 = 0.f, rs1 = 0.f;

    for (int t = 0; t < 64; t++) {
        __syncthreads();
        if (t + 3 < 64) {
            attn_pf(sb + ((t + 3) & 3) * ASTG, tid, hb, (t + 3) * 64, kh_g, vth, vtl);
            CPC();
            CPW(3);
        } else {
            CPW(0);
        }
        uint32_t sbs = sb + (t & 3) * ASTG;

        // per 16-kv slab: S (2-term) -> exp/pack -> PV (2-term)
#pragma unroll
        for (int tt = 0; tt < 4; tt++) {
            float s0[4] = {}, s1[4] = {};
#pragma unroll
            for (int ks = 0; ks < 4; ks++) {
                uint32_t addr = sbs + (tt * 16 + l15) * AP16 + (ks * 16 + 8 * lh) * 2;
                uint32_t h0, h1, h2, h3;
                LDSM4(h0, h1, h2, h3, addr);
                uint32_t b0[2] = {h0, h2}, b1[2] = {h1, h3};
                MMA16816(s0, qh[ks], b0);
                MMA16816(s0, ql[ks], b0);
                MMA16816(s1, qh[ks], b1);
                MMA16816(s1, ql[ks], b1);
            }

            float e0[4], e1[4];
#pragma unroll
            for (int e = 0; e < 4; e++) { EX2(e0[e], s0[e]); EX2(e1[e], s1[e]); }
            rs0 += e0[0] + e0[1] + e1[0] + e1[1];
            rs1 += e0[2] + e0[3] + e1[2] + e1[3];
            uint32_t pa[4];
            {
                __half2 h;
                h = __floats2half2_rn(e0[0], e0[1]); pa[0] = *(uint32_t*)&h;
                h = __floats2half2_rn(e0[2], e0[3]); pa[1] = *(uint32_t*)&h;
                h = __floats2half2_rn(e1[0], e1[1]); pa[2] = *(uint32_t*)&h;
                h = __floats2half2_rn(e1[2], e1[3]); pa[3] = *(uint32_t*)&h;
            }
#pragma unroll
            for (int jt = 0; jt < 4; jt++) {
                uint32_t addr = sbs + AMSZ + (jt * 16 + l15) * AP16 + (tt * 16 + 8 * lh) * 2;
                uint32_t h0, h1, h2, h3, l0, l1, l2, l3;
                LDSM4(h0, h1, h2, h3, addr);
                LDSM4(l0, l1, l2, l3, addr + AMSZ);
                uint32_t b0[2] = {h0, h2}, b1[2] = {h1, h3};
                uint32_t c0[2] = {l0, l2}, c1[2] = {l1, l3};
                MMA16816(oacc[2*jt],   pa, b0);
                MMA16816(oacc[2*jt],   pa, c0);
                MMA16816(oacc[2*jt+1], pa, b1);
                MMA16816(oacc[2*jt+1], pa, c1);
            }
        }
    }

    // rowsum reduce across the quad
    rs0 += __shfl_xor_sync(0xffffffffu, rs0, 1);
    rs0 += __shfl_xor_sync(0xffffffffu, rs0, 2);
    rs1 += __shfl_xor_sync(0xffffffffu, rs1, 1);
    rs1 += __shfl_xor_sync(0xffffffffu, rs1, 2);
    float i0 = 1.f / rs0, i1 = 1.f / rs1;

    size_t rbase = hb + (size_t)(m0 + wid * 16 + r) * DD;
#pragma unroll
    for (int j = 0; j < 8; j++) {
        float y00 = oacc[j][0] * i0, y01 = oacc[j][1] * i0;
        float y10 = oacc[j][2] * i1, y11 = oacc[j][3] * i1;
        __half2 p0 = __floats2half2_rn(y00, y01);
        __half2 q0 = __floats2half2_rn(y00 - __half2float(p0.x), y01 - __half2float(p0.y));
        __half2 p1 = __floats2half2_rn(y10, y11);
        __half2 q1 = __floats2half2_rn(y10 - __half2float(p1.x), y11 - __half2float(p1.y));
        *(uint32_t*)(oh_g + rbase + j * 8 + c2)          = *(uint32_t*)&p0;
        *(uint32_t*)(ol_g + rbase + j * 8 + c2)          = *(uint32_t*)&q0;
        *(uint32_t*)(oh_g + rbase + 8 * DD + j * 8 + c2) = *(uint32_t*)&p1;
        *(uint32_t*)(ol_g + rbase + 8 * DD + j * 8 + c2) = *(uint32_t*)&q1;
    }
}

// ------------------- host -------------------
extern "C" void kernel_launch(void* const* d_in, const int* in_sizes, int n_in,
                              void* d_out, int out_size) {
    const float* Q    = (const float*)d_in[0];
    const float* K    = (const float*)d_in[1];
    const float* V    = (const float*)d_in[2];
    const float* Wqk  = (const float*)d_in[3];
    const float* bqk  = (const float*)d_in[4];
    const float* Wv   = (const float*)d_in[5];
    const float* bv   = (const float*)d_in[6];
    const float* Wout = (const float*)d_in[7];
    const float* bout = (const float*)d_in[8];
    float* out = (float*)d_out;

    float* vf;
    __half *Qh,*Ql,*Kh,*Kl,*Vh,*Vl,*W1h,*W2h,*W3h;
    __half *qh,*ql,*kh,*vth,*vtl,*oh,*ol;
    cudaGetSymbolAddress((void**)&vf, g_vf);
    cudaGetSymbolAddress((void**)&Qh, g_Qh);   cudaGetSymbolAddress((void**)&Ql, g_Ql);
    cudaGetSymbolAddress((void**)&Kh, g_Kh);   cudaGetSymbolAddress((void**)&Kl, g_Kl);
    cudaGetSymbolAddress((void**)&Vh, g_Vh);   cudaGetSymbolAddress((void**)&Vl, g_Vl);
    cudaGetSymbolAddress((void**)&W1h, g_W1h); cudaGetSymbolAddress((void**)&W2h, g_W2h);
    cudaGetSymbolAddress((void**)&W3h, g_W3h);
    cudaGetSymbolAddress((void**)&qh, g_qh);   cudaGetSymbolAddress((void**)&ql, g_ql);
    cudaGetSymbolAddress((void**)&kh, g_kh);
    cudaGetSymbolAddress((void**)&vth, g_vth); cudaGetSymbolAddress((void**)&vtl, g_vtl);
    cudaGetSymbolAddress((void**)&oh, g_oh);   cudaGetSymbolAddress((void**)&ol, g_ol);

    cudaFuncSetAttribute(gemm_mma, cudaFuncAttributeMaxDynamicSharedMemorySize, G_SMEM);
    cudaFuncSetAttribute(attn_mma, cudaFuncAttributeMaxDynamicSharedMemorySize, A_SMEM);

    const int TB = 256;
    split2x3<<<dim3(TOT/4/TB, 3), TB>>>((const float4*)Q, (uint2*)Qh, (uint2*)Ql,
                                        (const float4*)K, (uint2*)Kh, (uint2*)Kl,
                                        (const float4*)V, (uint2*)Vh, (uint2*)Vl);
    cvt1x3<<<dim3(EE*EE/4/TB, 3), TB>>>((const float4*)Wqk,  (uint2*)W1h,
                                        (const float4*)Wv,   (uint2*)W2h,
                                        (const float4*)Wout, (uint2*)W3h);

    const float QSC = 0.125f * 1.4426950408889634f;  // 1/sqrt(D) * log2(e)
    GemmArgs gp = {};
    gp.Ah[0]=Qh; gp.Al[0]=Ql; gp.Wh[0]=W1h; gp.bias[0]=bqk;
    gp.Ch[0]=qh; gp.Cl[0]=ql; gp.scale[0]=QSC; gp.mode[0]=1;
    gp.Ah[1]=Kh; gp.Al[1]=Kl; gp.Wh[1]=W1h; gp.bias[1]=bqk;
    gp.Ch[1]=kh; gp.scale[1]=1.f; gp.mode[1]=2;
    gp.Ah[2]=Vh; gp.Al[2]=Vl; gp.Wh[2]=W2h; gp.bias[2]=bv;
    gp.Cf[2]=vf; gp.scale[2]=1.f; gp.mode[2]=0;
    gemm_mma<<<dim3(EE/128, SQ/128, 3), TB, G_SMEM>>>(gp);

    vtrans_split<<<dim3(SQ/32, DD/32, HH), dim3(32,32)>>>(vf, vth, vtl);

    attn_mma<<<dim3(SQ/128, HH), TB, A_SMEM>>>(qh, ql, kh, vth, vtl, oh, ol);

    GemmArgs go = {};
    go.Ah[0]=oh; go.Al[0]=ol; go.Wh[0]=W3h; go.bias[0]=bout;
    go.Cf[0]=out; go.scale[0]=1.f; go.mode[0]=0;
    gemm_mma<<<dim3(EE/128, SQ/128, 1), TB, G_SMEM>>>(go);
}

// round 12
// speedup vs baseline: 2.6306x; 1.8247x over previous
#include <cuda_runtime.h>
#include <cuda_fp16.h>
#include <cstdint>

#define SQ 4096
#define EE 512
#define HH 8
#define DD 64
#define HSZ (SQ*DD)
#define TOT (SQ*EE)

// ------------------- global scratch -------------------
__device__ float g_vf[TOT];
__device__ __half g_Qh[TOT], g_Kh[TOT], g_Vh[TOT];
__device__ __half g_W1h[EE*EE], g_W2h[EE*EE], g_W3h[EE*EE];
__device__ __half g_qh[TOT], g_kh[TOT], g_vth[TOT], g_oh[TOT];

// ------------------- helpers -------------------
__device__ __forceinline__ uint32_t smem_u32(const void* p) {
    uint32_t a;
    asm("{ .reg .u64 t; cvta.to.shared.u64 t, %1; cvt.u32.u64 %0, t; }" : "=r"(a) : "l"(p));
    return a;
}
#define LDSM4(R0,R1,R2,R3,ADDR) \
    asm volatile("ldmatrix.sync.aligned.m8n8.x4.shared.b16 {%0,%1,%2,%3}, [%4];" \
        : "=r"(R0),"=r"(R1),"=r"(R2),"=r"(R3) : "r"(ADDR))
#define MMA16816(C,A,B) \
    asm volatile("mma.sync.aligned.m16n8k16.row.col.f32.f16.f16.f32 " \
        "{%0,%1,%2,%3},{%4,%5,%6,%7},{%8,%9},{%0,%1,%2,%3};" \
        : "+f"((C)[0]),"+f"((C)[1]),"+f"((C)[2]),"+f"((C)[3]) \
        : "r"((A)[0]),"r"((A)[1]),"r"((A)[2]),"r"((A)[3]),"r"((B)[0]),"r"((B)[1]))
#define CPA16(DST,SRC) \
    asm volatile("cp.async.cg.shared.global [%0], [%1], 16;" :: "r"(DST), "l"(SRC) : "memory")
#define CPC() asm volatile("cp.async.commit_group;" ::: "memory")
#define CPW(N) asm volatile("cp.async.wait_group %0;" :: "n"(N) : "memory")
#define EX2(D,S) asm("ex2.approx.f32 %0, %1;" : "=f"(D) : "f"(S))

// ------------------- fp32 -> fp16 convert (3 tensors / launch) --------------
__global__ void cvt1x3(const float4* __restrict__ x0, uint2* __restrict__ h0,
                       const float4* __restrict__ x1, uint2* __restrict__ h1,
                       const float4* __restrict__ x2, uint2* __restrict__ h2) {
    const float4* x = blockIdx.y == 0 ? x0 : blockIdx.y == 1 ? x1 : x2;
    uint2* hi = blockIdx.y == 0 ? h0 : blockIdx.y == 1 ? h1 : h2;
    int i = blockIdx.x * blockDim.x + threadIdx.x;
    float4 v = x[i];
    __half2 a01 = __floats2half2_rn(v.x, v.y);
    __half2 a23 = __floats2half2_rn(v.z, v.w);
    uint2 hv;
    hv.x = *(uint32_t*)&a01; hv.y = *(uint32_t*)&a23;
    hi[i] = hv;
}

// per-head transpose of V (flat per-head chop — layout-correct): fp16 out
__global__ void vtrans_cvt(const float* __restrict__ vf, __half* __restrict__ vthi) {
    __shared__ float tile[32][33];
    int h = blockIdx.z, t0 = blockIdx.x * 32, d0 = blockIdx.y * 32;
    int tx = threadIdx.x, ty = threadIdx.y;
    tile[ty][tx] = vf[(size_t)h * HSZ + (size_t)(t0 + ty) * DD + d0 + tx];
    __syncthreads();
    vthi[(size_t)h * HSZ + (size_t)(d0 + ty) * SQ + t0 + tx] = __float2half_rn(tile[tx][ty]);
}

// ------------------- fp16 GEMM (K-chunk 16, 4-stage, race-free) --------------
#define GP16 48
#define GMSZ (128*GP16)                  // 6144 B / matrix
#define GSTG (2*GMSZ)                    // 12288 B / stage (A, W)
#define G_SMEM (4*GSTG)                  // 49152 B

struct GemmArgs {
    const __half *Ah[3], *Wh[3];
    const float* bias[3];
    float* Cf[3];
    __half *Ch[3];
    float scale[3];
    int mode[3];   // 0: fp32 out, 2: fp16 out
};

__device__ __forceinline__ void gemm_pf(
    uint32_t sbs, int tid, int m0, int n0, int ch,
    const __half* Ah, const __half* Wh)
{
#pragma unroll
    for (int q = 0; q < 2; q++) {
        int id = q * 256 + tid;
        int mat = id >> 8, rem = id & 255, row = rem >> 1, col = rem & 1;
        const __half* g = (mat == 0 ? Ah : Wh)
            + (size_t)((mat == 0 ? m0 : n0) + row) * EE + ch * 16 + col * 8;
        CPA16(sbs + mat * GMSZ + row * GP16 + col * 16, g);
    }
}

__global__ void __launch_bounds__(256, 2) gemm_mma(GemmArgs ga)
{
    extern __shared__ char sm[];
    uint32_t sb = smem_u32(sm);
    int tid = threadIdx.x, wid = tid >> 5, lane = tid & 31;
    int wm = wid & 3, wn = wid >> 2;
    int m0 = blockIdx.y * 128, n0 = blockIdx.x * 128;
    int z = blockIdx.z;
    int l15 = lane & 15, lh = lane >> 4;

    const __half *Ah = ga.Ah[z], *Wh = ga.Wh[z];
    const float* bias = ga.bias[z];
    float* Cf = ga.Cf[z];
    __half* Chi = ga.Ch[z];
    float scale = ga.scale[z];
    int mode = ga.mode[z];

    float acc[2][8][4] = {};

    gemm_pf(sb,            tid, m0, n0, 0, Ah, Wh); CPC();
    gemm_pf(sb + GSTG,     tid, m0, n0, 1, Ah, Wh); CPC();
    gemm_pf(sb + 2 * GSTG, tid, m0, n0, 2, Ah, Wh); CPC();

    for (int ch = 0; ch < 32; ch++) {
        // groups committed so far: 3 + ch. Wait until <=2 pending -> groups 0..ch done.
        CPW(2);
        __syncthreads();   // CTA-wide visibility of stage ch; all reads of stage (ch-1)&3 done
        if (ch + 3 < 32)
            gemm_pf(sb + ((ch + 3) & 3) * GSTG, tid, m0, n0, ch + 3, Ah, Wh);
        CPC();             // always commit (possibly empty) to keep group counting uniform
        uint32_t sbs = sb + (ch & 3) * GSTG;

        uint32_t ah[2][4];
#pragma unroll
        for (int mt = 0; mt < 2; mt++) {
            uint32_t addr = sbs + (wm * 32 + mt * 16 + l15) * GP16 + lh * 16;
            LDSM4(ah[mt][0], ah[mt][1], ah[mt][2], ah[mt][3], addr);
        }
#pragma unroll
        for (int jt = 0; jt < 4; jt++) {
            uint32_t addr = sbs + GMSZ + (wn * 64 + jt * 16 + l15) * GP16 + lh * 16;
            uint32_t h0, h1, h2, h3;
            LDSM4(h0, h1, h2, h3, addr);
            uint32_t b0[2] = {h0, h2}, b1[2] = {h1, h3};
#pragma unroll
            for (int mt = 0; mt < 2; mt++) {
                MMA16816(acc[mt][2*jt],   ah[mt], b0);
                MMA16816(acc[mt][2*jt+1], ah[mt], b1);
            }
        }
    }

    int r = lane >> 2, c2 = (lane & 3) * 2;
#pragma unroll
    for (int mt = 0; mt < 2; mt++) {
        size_t rbase = (size_t)(m0 + wm * 32 + mt * 16 + r) * EE + n0 + wn * 64;
#pragma unroll
        for (int j = 0; j < 8; j++) {
            float b0 = __ldg(bias + n0 + wn * 64 + j * 8 + c2);
            float b1 = __ldg(bias + n0 + wn * 64 + j * 8 + c2 + 1);
            float y00 = (acc[mt][j][0] + b0) * scale, y01 = (acc[mt][j][1] + b1) * scale;
            float y10 = (acc[mt][j][2] + b0) * scale, y11 = (acc[mt][j][3] + b1) * scale;
            if (mode == 0) {
                *(float2*)(Cf + rbase + j * 8 + c2)          = make_float2(y00, y01);
                *(float2*)(Cf + rbase + 8 * EE + j * 8 + c2) = make_float2(y10, y11);
            } else {
                __half2 p0 = __floats2half2_rn(y00, y01);
                __half2 p1 = __floats2half2_rn(y10, y11);
                *(uint32_t*)(Chi + rbase + j * 8 + c2)          = *(uint32_t*)&p0;
                *(uint32_t*)(Chi + rbase + 8 * EE + j * 8 + c2) = *(uint32_t*)&p1;
            }
        }
    }
}

// ------------------- fp16 flash attention (4-stage, race-free) ---------------
#define AP16 144
#define AMSZ (64*AP16)                   // 9216 B / matrix
#define ASTG (2*AMSZ)                    // 18432 B / stage (Kh, Vth)
#define A_SMEM (4*ASTG)                  // 73728 B

__device__ __forceinline__ void attn_pf(
    uint32_t sbs, int tid, size_t hb, int t0,
    const __half* kh, const __half* vth)
{
#pragma unroll
    for (int q = 0; q < 4; q++) {
        int id = q * 256 + tid;
        int mat = id >> 9, rem = id & 511, row = rem >> 3, col = rem & 7;
        const __half* g = (mat == 0)
            ? kh  + hb + (size_t)(t0 + row) * DD + col * 8
            : vth + hb + (size_t)row * SQ + t0 + col * 8;
        CPA16(sbs + mat * AMSZ + row * AP16 + col * 16, g);
    }
}

__global__ void __launch_bounds__(256, 2) attn_mma(
    const __half* __restrict__ qh_g, const __half* __restrict__ kh_g,
    const __half* __restrict__ vth, __half* __restrict__ oh_g)
{
    extern __shared__ char sm[];
    uint32_t sb = smem_u32(sm);
    int tid = threadIdx.x, wid = tid >> 5, lane = tid & 31;
    int head = blockIdx.y, m0 = blockIdx.x * 128;
    const size_t hb = (size_t)head * HSZ;
    int r = lane >> 2, c2 = (lane & 3) * 2;
    int l15 = lane & 15, lh = lane >> 4;

    attn_pf(sb,            tid, hb, 0,   kh_g, vth); CPC();
    attn_pf(sb + ASTG,     tid, hb, 64,  kh_g, vth); CPC();
    attn_pf(sb + 2 * ASTG, tid, hb, 128, kh_g, vth); CPC();

    // Q fragments (single fp16); q pre-scaled by 0.125*log2e
    uint32_t qh[4][4];
    {
        const __half* q0h = qh_g + hb + (size_t)(m0 + wid * 16) * DD;
#pragma unroll
        for (int ks = 0; ks < 4; ks++)
#pragma unroll
            for (int j = 0; j < 4; j++) {
                int rr = r + (j & 1) * 8;
                int kk = ks * 16 + c2 + (j >> 1) * 8;
                qh[ks][j] = *(const uint32_t*)(q0h + rr * DD + kk);
            }
    }

    float oacc[8][4] = {};
    float rs0 = 0.f, rs1 = 0.f;

    for (int t = 0; t < 64; t++) {
        // groups committed: 3 + t. Wait until <=2 pending -> groups 0..t done.
        CPW(2);
        __syncthreads();   // visibility of stage t to all threads; stage (t-1)&3 reads done
        if (t + 3 < 64)
            attn_pf(sb + ((t + 3) & 3) * ASTG, tid, hb, (t + 3) * 64, kh_g, vth);
        CPC();             // always commit (possibly empty)
        uint32_t sbs = sb + (t & 3) * ASTG;

        // per 16-kv slab: S -> exp/pack -> PV (all single-term)
#pragma unroll
        for (int tt = 0; tt < 4; tt++) {
            float s0[4] = {}, s1[4] = {};
#pragma unroll
            for (int ks = 0; ks < 4; ks++) {
                uint32_t addr = sbs + (tt * 16 + l15) * AP16 + (ks * 16 + 8 * lh) * 2;
                uint32_t h0, h1, h2, h3;
                LDSM4(h0, h1, h2, h3, addr);
                uint32_t b0[2] = {h0, h2}, b1[2] = {h1, h3};
                MMA16816(s0, qh[ks], b0);
                MMA16816(s1, qh[ks], b1);
            }

            float e0[4], e1[4];
#pragma unroll
            for (int e = 0; e < 4; e++) { EX2(e0[e], s0[e]); EX2(e1[e], s1[e]); }
            rs0 += e0[0] + e0[1] + e1[0] + e1[1];
            rs1 += e0[2] + e0[3] + e1[2] + e1[3];
            uint32_t pa[4];
            {
                __half2 h;
                h = __floats2half2_rn(e0[0], e0[1]); pa[0] = *(uint32_t*)&h;
                h = __floats2half2_rn(e0[2], e0[3]); pa[1] = *(uint32_t*)&h;
                h = __floats2half2_rn(e1[0], e1[1]); pa[2] = *(uint32_t*)&h;
                h = __floats2half2_rn(e1[2], e1[3]); pa[3] = *(uint32_t*)&h;
            }
#pragma unroll
            for (int jt = 0; jt < 4; jt++) {
                uint32_t addr = sbs + AMSZ + (jt * 16 + l15) * AP16 + (tt * 16 + 8 * lh) * 2;
                uint32_t h0, h1, h2, h3;
                LDSM4(h0, h1, h2, h3, addr);
                uint32_t b0[2] = {h0, h2}, b1[2] = {h1, h3};
                MMA16816(oacc[2*jt],   pa, b0);
                MMA16816(oacc[2*jt+1], pa, b1);
            }
        }
    }

    // rowsum reduce across the quad
    rs0 += __shfl_xor_sync(0xffffffffu, rs0, 1);
    rs0 += __shfl_xor_sync(0xffffffffu, rs0, 2);
    rs1 += __shfl_xor_sync(0xffffffffu, rs1, 1);
    rs1 += __shfl_xor_sync(0xffffffffu, rs1, 2);
    float i0 = 1.f / rs0, i1 = 1.f / rs1;

    size_t rbase = hb + (size_t)(m0 + wid * 16 + r) * DD;
#pragma unroll
    for (int j = 0; j < 8; j++) {
        __half2 p0 = __floats2half2_rn(oacc[j][0] * i0, oacc[j][1] * i0);
        __half2 p1 = __floats2half2_rn(oacc[j][2] * i1, oacc[j][3] * i1);
        *(uint32_t*)(oh_g + rbase + j * 8 + c2)          = *(uint32_t*)&p0;
        *(uint32_t*)(oh_g + rbase + 8 * DD + j * 8 + c2) = *(uint32_t*)&p1;
    }
}

// ------------------- host -------------------
extern "C" void kernel_launch(void* const* d_in, const int* in_sizes, int n_in,
                              void* d_out, int out_size) {
    const float* Q    = (const float*)d_in[0];
    const float* K    = (const float*)d_in[1];
    const float* V    = (const float*)d_in[2];
    const float* Wqk  = (const float*)d_in[3];
    const float* bqk  = (const float*)d_in[4];
    const float* Wv   = (const float*)d_in[5];
    const float* bv   = (const float*)d_in[6];
    const float* Wout = (const float*)d_in[7];
    const float* bout = (const float*)d_in[8];
    float* out = (float*)d_out;

    float* vf;
    __half *Qh,*Kh,*Vh,*W1h,*W2h,*W3h,*qh,*kh,*vth,*oh;
    cudaGetSymbolAddress((void**)&vf, g_vf);
    cudaGetSymbolAddress((void**)&Qh, g_Qh);   cudaGetSymbolAddress((void**)&Kh, g_Kh);
    cudaGetSymbolAddress((void**)&Vh, g_Vh);
    cudaGetSymbolAddress((void**)&W1h, g_W1h); cudaGetSymbolAddress((void**)&W2h, g_W2h);
    cudaGetSymbolAddress((void**)&W3h, g_W3h);
    cudaGetSymbolAddress((void**)&qh, g_qh);   cudaGetSymbolAddress((void**)&kh, g_kh);
    cudaGetSymbolAddress((void**)&vth, g_vth); cudaGetSymbolAddress((void**)&oh, g_oh);

    cudaFuncSetAttribute(gemm_mma, cudaFuncAttributeMaxDynamicSharedMemorySize, G_SMEM);
    cudaFuncSetAttribute(attn_mma, cudaFuncAttributeMaxDynamicSharedMemorySize, A_SMEM);

    const int TB = 256;
    cvt1x3<<<dim3(TOT/4/TB, 3), TB>>>((const float4*)Q, (uint2*)Qh,
                                      (const float4*)K, (uint2*)Kh,
                                      (const float4*)V, (uint2*)Vh);
    cvt1x3<<<dim3(EE*EE/4/TB, 3), TB>>>((const float4*)Wqk,  (uint2*)W1h,
                                        (const float4*)Wv,   (uint2*)W2h,
                                        (const float4*)Wout, (uint2*)W3h);

    const float QSC = 0.125f * 1.4426950408889634f;  // 1/sqrt(D) * log2(e)
    GemmArgs gp = {};
    gp.Ah[0]=Qh; gp.Wh[0]=W1h; gp.bias[0]=bqk; gp.Ch[0]=qh; gp.scale[0]=QSC; gp.mode[0]=2;
    gp.Ah[1]=Kh; gp.Wh[1]=W1h; gp.bias[1]=bqk; gp.Ch[1]=kh; gp.scale[1]=1.f; gp.mode[1]=2;
    gp.Ah[2]=Vh; gp.Wh[2]=W2h; gp.bias[2]=bv;  gp.Cf[2]=vf; gp.scale[2]=1.f; gp.mode[2]=0;
    gemm_mma<<<dim3(EE/128, SQ/128, 3), TB, G_SMEM>>>(gp);

    vtrans_cvt<<<dim3(SQ/32, DD/32, HH), dim3(32,32)>>>(vf, vth);

    attn_mma<<<dim3(SQ/128, HH), TB, A_SMEM>>>(qh, kh, vth, oh);

    GemmArgs go = {};
    go.Ah[0]=oh; go.Wh[0]=W3h; go.bias[0]=bout; go.Cf[0]=out; go.scale[0]=1.f; go.mode[0]=0;
    gemm_mma<<<dim3(EE/128, SQ/128, 1), TB, G_SMEM>>>(go);
}

// round 13
// speedup vs baseline: 2.6521x; 1.0082x over previous
#include <cuda_runtime.h>
#include <cuda_fp16.h>
#include <cstdint>

#define SQ 4096
#define EE 512
#define HH 8
#define DD 64
#define HSZ (SQ*DD)
#define TOT (SQ*EE)

// ------------------- global scratch -------------------
__device__ float g_vf[TOT];   // reused as fp16 buffer for V projection output
__device__ __half g_Qh[TOT], g_Kh[TOT], g_Vh[TOT];
__device__ __half g_W1h[EE*EE], g_W2h[EE*EE], g_W3h[EE*EE];
__device__ __half g_qh[TOT], g_kh[TOT], g_vth[TOT], g_oh[TOT];

// ------------------- helpers -------------------
__device__ __forceinline__ uint32_t smem_u32(const void* p) {
    uint32_t a;
    asm("{ .reg .u64 t; cvta.to.shared.u64 t, %1; cvt.u32.u64 %0, t; }" : "=r"(a) : "l"(p));
    return a;
}
#define LDSM4(R0,R1,R2,R3,ADDR) \
    asm volatile("ldmatrix.sync.aligned.m8n8.x4.shared.b16 {%0,%1,%2,%3}, [%4];" \
        : "=r"(R0),"=r"(R1),"=r"(R2),"=r"(R3) : "r"(ADDR))
#define MMA16816(C,A,B) \
    asm volatile("mma.sync.aligned.m16n8k16.row.col.f32.f16.f16.f32 " \
        "{%0,%1,%2,%3},{%4,%5,%6,%7},{%8,%9},{%0,%1,%2,%3};" \
        : "+f"((C)[0]),"+f"((C)[1]),"+f"((C)[2]),"+f"((C)[3]) \
        : "r"((A)[0]),"r"((A)[1]),"r"((A)[2]),"r"((A)[3]),"r"((B)[0]),"r"((B)[1]))
#define CPA16(DST,SRC) \
    asm volatile("cp.async.cg.shared.global [%0], [%1], 16;" :: "r"(DST), "l"(SRC) : "memory")
#define CPC() asm volatile("cp.async.commit_group;" ::: "memory")
#define CPW(N) asm volatile("cp.async.wait_group %0;" :: "n"(N) : "memory")
#define EX2H2(D) asm("ex2.approx.f16x2 %0, %0;" : "+r"(D))

// ------------------- fp32 -> fp16 convert (3 tensors / launch) --------------
__global__ void cvt1x3(const float4* __restrict__ x0, uint2* __restrict__ h0,
                       const float4* __restrict__ x1, uint2* __restrict__ h1,
                       const float4* __restrict__ x2, uint2* __restrict__ h2) {
    const float4* x = blockIdx.y == 0 ? x0 : blockIdx.y == 1 ? x1 : x2;
    uint2* hi = blockIdx.y == 0 ? h0 : blockIdx.y == 1 ? h1 : h2;
    int i = blockIdx.x * blockDim.x + threadIdx.x;
    float4 v = x[i];
    __half2 a01 = __floats2half2_rn(v.x, v.y);
    __half2 a23 = __floats2half2_rn(v.z, v.w);
    uint2 hv;
    hv.x = *(uint32_t*)&a01; hv.y = *(uint32_t*)&a23;
    hi[i] = hv;
}

// per-head transpose of V (flat per-head chop — layout-correct), fp16 in/out
__global__ void vtrans_h(const __half* __restrict__ vf16, __half* __restrict__ vthi) {
    __shared__ __half tile[32][34];
    int h = blockIdx.z, t0 = blockIdx.x * 32, d0 = blockIdx.y * 32;
    int tx = threadIdx.x, ty = threadIdx.y;
    tile[ty][tx] = vf16[(size_t)h * HSZ + (size_t)(t0 + ty) * DD + d0 + tx];
    __syncthreads();
    vthi[(size_t)h * HSZ + (size_t)(d0 + ty) * SQ + t0 + tx] = tile[tx][ty];
}

// ------------------- fp16 GEMM (K-chunk 16, 4-stage, race-free) --------------
#define GP16 48
#define GMSZ (128*GP16)                  // 6144 B / matrix
#define GSTG (2*GMSZ)                    // 12288 B / stage (A, W)
#define G_SMEM (4*GSTG)                  // 49152 B

struct GemmArgs {
    const __half *Ah[3], *Wh[3];
    const float* bias[3];
    float* Cf[3];
    __half *Ch[3];
    float scale[3];
    int mode[3];   // 0: fp32 out, 2: fp16 out
};

__device__ __forceinline__ void gemm_pf(
    uint32_t sbs, int tid, int m0, int n0, int ch,
    const __half* Ah, const __half* Wh)
{
#pragma unroll
    for (int q = 0; q < 2; q++) {
        int id = q * 256 + tid;
        int mat = id >> 8, rem = id & 255, row = rem >> 1, col = rem & 1;
        const __half* g = (mat == 0 ? Ah : Wh)
            + (size_t)((mat == 0 ? m0 : n0) + row) * EE + ch * 16 + col * 8;
        CPA16(sbs + mat * GMSZ + row * GP16 + col * 16, g);
    }
}

__global__ void __launch_bounds__(256, 2) gemm_mma(GemmArgs ga)
{
    extern __shared__ char sm[];
    uint32_t sb = smem_u32(sm);
    int tid = threadIdx.x, wid = tid >> 5, lane = tid & 31;
    int wm = wid & 3, wn = wid >> 2;
    int m0 = blockIdx.y * 128, n0 = blockIdx.x * 128;
    int z = blockIdx.z;
    int l15 = lane & 15, lh = lane >> 4;

    const __half *Ah = ga.Ah[z], *Wh = ga.Wh[z];
    const float* bias = ga.bias[z];
    float* Cf = ga.Cf[z];
    __half* Chi = ga.Ch[z];
    float scale = ga.scale[z];
    int mode = ga.mode[z];

    float acc[2][8][4] = {};

    gemm_pf(sb,            tid, m0, n0, 0, Ah, Wh); CPC();
    gemm_pf(sb + GSTG,     tid, m0, n0, 1, Ah, Wh); CPC();
    gemm_pf(sb + 2 * GSTG, tid, m0, n0, 2, Ah, Wh); CPC();

    for (int ch = 0; ch < 32; ch++) {
        CPW(2);
        __syncthreads();
        if (ch + 3 < 32)
            gemm_pf(sb + ((ch + 3) & 3) * GSTG, tid, m0, n0, ch + 3, Ah, Wh);
        CPC();
        uint32_t sbs = sb + (ch & 3) * GSTG;

        uint32_t ah[2][4];
#pragma unroll
        for (int mt = 0; mt < 2; mt++) {
            uint32_t addr = sbs + (wm * 32 + mt * 16 + l15) * GP16 + lh * 16;
            LDSM4(ah[mt][0], ah[mt][1], ah[mt][2], ah[mt][3], addr);
        }
#pragma unroll
        for (int jt = 0; jt < 4; jt++) {
            uint32_t addr = sbs + GMSZ + (wn * 64 + jt * 16 + l15) * GP16 + lh * 16;
            uint32_t h0, h1, h2, h3;
            LDSM4(h0, h1, h2, h3, addr);
            uint32_t b0[2] = {h0, h2}, b1[2] = {h1, h3};
#pragma unroll
            for (int mt = 0; mt < 2; mt++) {
                MMA16816(acc[mt][2*jt],   ah[mt], b0);
                MMA16816(acc[mt][2*jt+1], ah[mt], b1);
            }
        }
    }

    int r = lane >> 2, c2 = (lane & 3) * 2;
#pragma unroll
    for (int mt = 0; mt < 2; mt++) {
        size_t rbase = (size_t)(m0 + wm * 32 + mt * 16 + r) * EE + n0 + wn * 64;
#pragma unroll
        for (int j = 0; j < 8; j++) {
            float b0 = __ldg(bias + n0 + wn * 64 + j * 8 + c2);
            float b1 = __ldg(bias + n0 + wn * 64 + j * 8 + c2 + 1);
            float y00 = (acc[mt][j][0] + b0) * scale, y01 = (acc[mt][j][1] + b1) * scale;
            float y10 = (acc[mt][j][2] + b0) * scale, y11 = (acc[mt][j][3] + b1) * scale;
            if (mode == 0) {
                *(float2*)(Cf + rbase + j * 8 + c2)          = make_float2(y00, y01);
                *(float2*)(Cf + rbase + 8 * EE + j * 8 + c2) = make_float2(y10, y11);
            } else {
                __half2 p0 = __floats2half2_rn(y00, y01);
                __half2 p1 = __floats2half2_rn(y10, y11);
                *(uint32_t*)(Chi + rbase + j * 8 + c2)          = *(uint32_t*)&p0;
                *(uint32_t*)(Chi + rbase + 8 * EE + j * 8 + c2) = *(uint32_t*)&p1;
            }
        }
    }
}

// ------------------- fp16 flash attention (4-stage, h2 exp) ------------------
#define AP16 144
#define AMSZ (64*AP16)                   // 9216 B / matrix
#define ASTG (2*AMSZ)                    // 18432 B / stage (Kh, Vth)
#define A_SMEM (4*ASTG)                  // 73728 B

__device__ __forceinline__ void attn_pf(
    uint32_t sbs, int tid, size_t hb, int t0,
    const __half* kh, const __half* vth)
{
#pragma unroll
    for (int q = 0; q < 4; q++) {
        int id = q * 256 + tid;
        int mat = id >> 9, rem = id & 511, row = rem >> 3, col = rem & 7;
        const __half* g = (mat == 0)
            ? kh  + hb + (size_t)(t0 + row) * DD + col * 8
            : vth + hb + (size_t)row * SQ + t0 + col * 8;
        CPA16(sbs + mat * AMSZ + row * AP16 + col * 16, g);
    }
}

__global__ void __launch_bounds__(256, 2) attn_mma(
    const __half* __restrict__ qh_g, const __half* __restrict__ kh_g,
    const __half* __restrict__ vth, __half* __restrict__ oh_g)
{
    extern __shared__ char sm[];
    uint32_t sb = smem_u32(sm);
    int tid = threadIdx.x, wid = tid >> 5, lane = tid & 31;
    int head = blockIdx.y, m0 = blockIdx.x * 128;
    const size_t hb = (size_t)head * HSZ;
    int r = lane >> 2, c2 = (lane & 3) * 2;
    int l15 = lane & 15, lh = lane >> 4;

    attn_pf(sb,            tid, hb, 0,   kh_g, vth); CPC();
    attn_pf(sb + ASTG,     tid, hb, 64,  kh_g, vth); CPC();
    attn_pf(sb + 2 * ASTG, tid, hb, 128, kh_g, vth); CPC();

    // Q fragments (single fp16); q pre-scaled by 0.125*log2e
    uint32_t qh[4][4];
    {
        const __half* q0h = qh_g + hb + (size_t)(m0 + wid * 16) * DD;
#pragma unroll
        for (int ks = 0; ks < 4; ks++)
#pragma unroll
            for (int j = 0; j < 4; j++) {
                int rr = r + (j & 1) * 8;
                int kk = ks * 16 + c2 + (j >> 1) * 8;
                qh[ks][j] = *(const uint32_t*)(q0h + rr * DD + kk);
            }
    }

    float oacc[8][4] = {};
    float rs0 = 0.f, rs1 = 0.f;

    for (int t = 0; t < 64; t++) {
        CPW(2);
        __syncthreads();
        if (t + 3 < 64)
            attn_pf(sb + ((t + 3) & 3) * ASTG, tid, hb, (t + 3) * 64, kh_g, vth);
        CPC();
        uint32_t sbs = sb + (t & 3) * ASTG;

        // per 16-kv slab: S -> exp(f16x2) -> PV
#pragma unroll
        for (int tt = 0; tt < 4; tt++) {
            float s0[4] = {}, s1[4] = {};
#pragma unroll
            for (int ks = 0; ks < 4; ks++) {
                uint32_t addr = sbs + (tt * 16 + l15) * AP16 + (ks * 16 + 8 * lh) * 2;
                uint32_t h0, h1, h2, h3;
                LDSM4(h0, h1, h2, h3, addr);
                uint32_t b0[2] = {h0, h2}, b1[2] = {h1, h3};
                MMA16816(s0, qh[ks], b0);
                MMA16816(s1, qh[ks], b1);
            }

            // pack scores -> half2, exp2 in f16x2 (one MUFU per pair)
            uint32_t pa[4];
            {
                __half2 hh;
                hh = __floats2half2_rn(s0[0], s0[1]); pa[0] = *(uint32_t*)&hh;
                hh = __floats2half2_rn(s0[2], s0[3]); pa[1] = *(uint32_t*)&hh;
                hh = __floats2half2_rn(s1[0], s1[1]); pa[2] = *(uint32_t*)&hh;
                hh = __floats2half2_rn(s1[2], s1[3]); pa[3] = *(uint32_t*)&hh;
            }
            EX2H2(pa[0]); EX2H2(pa[1]); EX2H2(pa[2]); EX2H2(pa[3]);
            {
                float2 f0 = __half22float2(*(__half2*)&pa[0]);
                float2 f1 = __half22float2(*(__half2*)&pa[1]);
                float2 f2 = __half22float2(*(__half2*)&pa[2]);
                float2 f3 = __half22float2(*(__half2*)&pa[3]);
                rs0 += f0.x + f0.y + f2.x + f2.y;   // rows r
                rs1 += f1.x + f1.y + f3.x + f3.y;   // rows r+8
            }
#pragma unroll
            for (int jt = 0; jt < 4; jt++) {
                uint32_t addr = sbs + AMSZ + (jt * 16 + l15) * AP16 + (tt * 16 + 8 * lh) * 2;
                uint32_t h0, h1, h2, h3;
                LDSM4(h0, h1, h2, h3, addr);
                uint32_t b0[2] = {h0, h2}, b1[2] = {h1, h3};
                MMA16816(oacc[2*jt],   pa, b0);
                MMA16816(oacc[2*jt+1], pa, b1);
            }
        }
    }

    // rowsum reduce across the quad
    rs0 += __shfl_xor_sync(0xffffffffu, rs0, 1);
    rs0 += __shfl_xor_sync(0xffffffffu, rs0, 2);
    rs1 += __shfl_xor_sync(0xffffffffu, rs1, 1);
    rs1 += __shfl_xor_sync(0xffffffffu, rs1, 2);
    float i0 = 1.f / rs0, i1 = 1.f / rs1;

    size_t rbase = hb + (size_t)(m0 + wid * 16 + r) * DD;
#pragma unroll
    for (int j = 0; j < 8; j++) {
        __half2 p0 = __floats2half2_rn(oacc[j][0] * i0, oacc[j][1] * i0);
        __half2 p1 = __floats2half2_rn(oacc[j][2] * i1, oacc[j][3] * i1);
        *(uint32_t*)(oh_g + rbase + j * 8 + c2)          = *(uint32_t*)&p0;
        *(uint32_t*)(oh_g + rbase + 8 * DD + j * 8 + c2) = *(uint32_t*)&p1;
    }
}

// ------------------- host -------------------
extern "C" void kernel_launch(void* const* d_in, const int* in_sizes, int n_in,
                              void* d_out, int out_size) {
    const float* Q    = (const float*)d_in[0];
    const float* K    = (const float*)d_in[1];
    const float* V    = (const float*)d_in[2];
    const float* Wqk  = (const float*)d_in[3];
    const float* bqk  = (const float*)d_in[4];
    const float* Wv   = (const float*)d_in[5];
    const float* bv   = (const float*)d_in[6];
    const float* Wout = (const float*)d_in[7];
    const float* bout = (const float*)d_in[8];
    float* out = (float*)d_out;

    float* vf;
    __half *Qh,*Kh,*Vh,*W1h,*W2h,*W3h,*qh,*kh,*vth,*oh;
    cudaGetSymbolAddress((void**)&vf, g_vf);
    cudaGetSymbolAddress((void**)&Qh, g_Qh);   cudaGetSymbolAddress((void**)&Kh, g_Kh);
    cudaGetSymbolAddress((void**)&Vh, g_Vh);
    cudaGetSymbolAddress((void**)&W1h, g_W1h); cudaGetSymbolAddress((void**)&W2h, g_W2h);
    cudaGetSymbolAddress((void**)&W3h, g_W3h);
    cudaGetSymbolAddress((void**)&qh, g_qh);   cudaGetSymbolAddress((void**)&kh, g_kh);
    cudaGetSymbolAddress((void**)&vth, g_vth); cudaGetSymbolAddress((void**)&oh, g_oh);
    __half* vf16 = (__half*)vf;   // reuse fp32 scratch as fp16 V-projection buffer

    cudaFuncSetAttribute(gemm_mma, cudaFuncAttributeMaxDynamicSharedMemorySize, G_SMEM);
    cudaFuncSetAttribute(attn_mma, cudaFuncAttributeMaxDynamicSharedMemorySize, A_SMEM);

    const int TB = 256;
    cvt1x3<<<dim3(TOT/4/TB, 3), TB>>>((const float4*)Q, (uint2*)Qh,
                                      (const float4*)K, (uint2*)Kh,
                                      (const float4*)V, (uint2*)Vh);
    cvt1x3<<<dim3(EE*EE/4/TB, 3), TB>>>((const float4*)Wqk,  (uint2*)W1h,
                                        (const float4*)Wv,   (uint2*)W2h,
                                        (const float4*)Wout, (uint2*)W3h);

    const float QSC = 0.125f * 1.4426950408889634f;  // 1/sqrt(D) * log2(e)
    GemmArgs gp = {};
    gp.Ah[0]=Qh; gp.Wh[0]=W1h; gp.bias[0]=bqk; gp.Ch[0]=qh;   gp.scale[0]=QSC; gp.mode[0]=2;
    gp.Ah[1]=Kh; gp.Wh[1]=W1h; gp.bias[1]=bqk; gp.Ch[1]=kh;   gp.scale[1]=1.f; gp.mode[1]=2;
    gp.Ah[2]=Vh; gp.Wh[2]=W2h; gp.bias[2]=bv;  gp.Ch[2]=vf16; gp.scale[2]=1.f; gp.mode[2]=2;
    gemm_mma<<<dim3(EE/128, SQ/128, 3), TB, G_SMEM>>>(gp);

    vtrans_h<<<dim3(SQ/32, DD/32, HH), dim3(32,32)>>>(vf16, vth);

    attn_mma<<<dim3(SQ/128, HH), TB, A_SMEM>>>(qh, kh, vth, oh);

    GemmArgs go = {};
    go.Ah[0]=oh; go.Wh[0]=W3h; go.bias[0]=bout; go.Cf[0]=out; go.scale[0]=1.f; go.mode[0]=0;
    gemm_mma<<<dim3(EE/128, SQ/128, 1), TB, G_SMEM>>>(go);
}

// round 14
// speedup vs baseline: 2.7077x; 1.0210x over previous
#include <cuda_runtime.h>
#include <cuda_fp16.h>
#include <cstdint>

#define SQ 4096
#define EE 512
#define HH 8
#define DD 64
#define HSZ (SQ*DD)
#define TOT (SQ*EE)

// ------------------- global scratch -------------------
__device__ float g_vf[TOT];   // reused as fp16 buffer for V projection output
__device__ __half g_Qh[TOT], g_Kh[TOT], g_Vh[TOT];
__device__ __half g_W1h[EE*EE], g_W2h[EE*EE], g_W3h[EE*EE];
__device__ __half g_qh[TOT], g_kh[TOT], g_vth[TOT], g_oh[TOT];

// ------------------- helpers -------------------
__device__ __forceinline__ uint32_t smem_u32(const void* p) {
    uint32_t a;
    asm("{ .reg .u64 t; cvta.to.shared.u64 t, %1; cvt.u32.u64 %0, t; }" : "=r"(a) : "l"(p));
    return a;
}
#define LDSM4(R0,R1,R2,R3,ADDR) \
    asm volatile("ldmatrix.sync.aligned.m8n8.x4.shared.b16 {%0,%1,%2,%3}, [%4];" \
        : "=r"(R0),"=r"(R1),"=r"(R2),"=r"(R3) : "r"(ADDR))
#define MMA16816(C,A,B) \
    asm volatile("mma.sync.aligned.m16n8k16.row.col.f32.f16.f16.f32 " \
        "{%0,%1,%2,%3},{%4,%5,%6,%7},{%8,%9},{%0,%1,%2,%3};" \
        : "+f"((C)[0]),"+f"((C)[1]),"+f"((C)[2]),"+f"((C)[3]) \
        : "r"((A)[0]),"r"((A)[1]),"r"((A)[2]),"r"((A)[3]),"r"((B)[0]),"r"((B)[1]))
#define CPA16(DST,SRC) \
    asm volatile("cp.async.cg.shared.global [%0], [%1], 16;" :: "r"(DST), "l"(SRC) : "memory")
#define CPC() asm volatile("cp.async.commit_group;" ::: "memory")
#define CPW(N) asm volatile("cp.async.wait_group %0;" :: "n"(N) : "memory")
#define EX2H2(D) asm("ex2.approx.f16x2 %0, %0;" : "+r"(D))

// ------------------- fp32 -> fp16 convert (3 tensors / launch) --------------
__global__ void cvt1x3(const float4* __restrict__ x0, uint2* __restrict__ h0,
                       const float4* __restrict__ x1, uint2* __restrict__ h1,
                       const float4* __restrict__ x2, uint2* __restrict__ h2) {
    const float4* x = blockIdx.y == 0 ? x0 : blockIdx.y == 1 ? x1 : x2;
    uint2* hi = blockIdx.y == 0 ? h0 : blockIdx.y == 1 ? h1 : h2;
    int i = blockIdx.x * blockDim.x + threadIdx.x;
    float4 v = x[i];
    __half2 a01 = __floats2half2_rn(v.x, v.y);
    __half2 a23 = __floats2half2_rn(v.z, v.w);
    uint2 hv;
    hv.x = *(uint32_t*)&a01; hv.y = *(uint32_t*)&a23;
    hi[i] = hv;
}

// per-head transpose of V (flat per-head chop — layout-correct), fp16 in/out
__global__ void vtrans_h(const __half* __restrict__ vf16, __half* __restrict__ vthi) {
    __shared__ __half tile[32][34];
    int h = blockIdx.z, t0 = blockIdx.x * 32, d0 = blockIdx.y * 32;
    int tx = threadIdx.x, ty = threadIdx.y;
    tile[ty][tx] = vf16[(size_t)h * HSZ + (size_t)(t0 + ty) * DD + d0 + tx];
    __syncthreads();
    vthi[(size_t)h * HSZ + (size_t)(d0 + ty) * SQ + t0 + tx] = tile[tx][ty];
}

// ------------------- fp16 GEMM (K-chunk 16, 4-stage, race-free) --------------
#define GP16 48
#define GMSZ (128*GP16)                  // 6144 B / matrix
#define GSTG (2*GMSZ)                    // 12288 B / stage (A, W)
#define G_SMEM (4*GSTG)                  // 49152 B

struct GemmArgs {
    const __half *Ah[3], *Wh[3];
    const float* bias[3];
    float* Cf[3];
    __half *Ch[3];
    float scale[3];
    int mode[3];   // 0: fp32 out, 2: fp16 out
};

__device__ __forceinline__ void gemm_pf(
    uint32_t sbs, int tid, int m0, int n0, int ch,
    const __half* Ah, const __half* Wh)
{
#pragma unroll
    for (int q = 0; q < 2; q++) {
        int id = q * 256 + tid;
        int mat = id >> 8, rem = id & 255, row = rem >> 1, col = rem & 1;
        const __half* g = (mat == 0 ? Ah : Wh)
            + (size_t)((mat == 0 ? m0 : n0) + row) * EE + ch * 16 + col * 8;
        CPA16(sbs + mat * GMSZ + row * GP16 + col * 16, g);
    }
}

__global__ void __launch_bounds__(256, 2) gemm_mma(GemmArgs ga)
{
    extern __shared__ char sm[];
    uint32_t sb = smem_u32(sm);
    int tid = threadIdx.x, wid = tid >> 5, lane = tid & 31;
    int wm = wid & 3, wn = wid >> 2;
    int m0 = blockIdx.y * 128, n0 = blockIdx.x * 128;
    int z = blockIdx.z;
    int l15 = lane & 15, lh = lane >> 4;

    const __half *Ah = ga.Ah[z], *Wh = ga.Wh[z];
    const float* bias = ga.bias[z];
    float* Cf = ga.Cf[z];
    __half* Chi = ga.Ch[z];
    float scale = ga.scale[z];
    int mode = ga.mode[z];

    float acc[2][8][4] = {};

    gemm_pf(sb,            tid, m0, n0, 0, Ah, Wh); CPC();
    gemm_pf(sb + GSTG,     tid, m0, n0, 1, Ah, Wh); CPC();
    gemm_pf(sb + 2 * GSTG, tid, m0, n0, 2, Ah, Wh); CPC();

    for (int ch = 0; ch < 32; ch++) {
        CPW(2);
        __syncthreads();
        if (ch + 3 < 32)
            gemm_pf(sb + ((ch + 3) & 3) * GSTG, tid, m0, n0, ch + 3, Ah, Wh);
        CPC();
        uint32_t sbs = sb + (ch & 3) * GSTG;

        uint32_t ah[2][4];
#pragma unroll
        for (int mt = 0; mt < 2; mt++) {
            uint32_t addr = sbs + (wm * 32 + mt * 16 + l15) * GP16 + lh * 16;
            LDSM4(ah[mt][0], ah[mt][1], ah[mt][2], ah[mt][3], addr);
        }
#pragma unroll
        for (int jt = 0; jt < 4; jt++) {
            uint32_t addr = sbs + GMSZ + (wn * 64 + jt * 16 + l15) * GP16 + lh * 16;
            uint32_t h0, h1, h2, h3;
            LDSM4(h0, h1, h2, h3, addr);
            uint32_t b0[2] = {h0, h2}, b1[2] = {h1, h3};
#pragma unroll
            for (int mt = 0; mt < 2; mt++) {
                MMA16816(acc[mt][2*jt],   ah[mt], b0);
                MMA16816(acc[mt][2*jt+1], ah[mt], b1);
            }
        }
    }

    int r = lane >> 2, c2 = (lane & 3) * 2;
#pragma unroll
    for (int mt = 0; mt < 2; mt++) {
        size_t rbase = (size_t)(m0 + wm * 32 + mt * 16 + r) * EE + n0 + wn * 64;
#pragma unroll
        for (int j = 0; j < 8; j++) {
            float b0 = __ldg(bias + n0 + wn * 64 + j * 8 + c2);
            float b1 = __ldg(bias + n0 + wn * 64 + j * 8 + c2 + 1);
            float y00 = (acc[mt][j][0] + b0) * scale, y01 = (acc[mt][j][1] + b1) * scale;
            float y10 = (acc[mt][j][2] + b0) * scale, y11 = (acc[mt][j][3] + b1) * scale;
            if (mode == 0) {
                *(float2*)(Cf + rbase + j * 8 + c2)          = make_float2(y00, y01);
                *(float2*)(Cf + rbase + 8 * EE + j * 8 + c2) = make_float2(y10, y11);
            } else {
                __half2 p0 = __floats2half2_rn(y00, y01);
                __half2 p1 = __floats2half2_rn(y10, y11);
                *(uint32_t*)(Chi + rbase + j * 8 + c2)          = *(uint32_t*)&p0;
                *(uint32_t*)(Chi + rbase + 8 * EE + j * 8 + c2) = *(uint32_t*)&p1;
            }
        }
    }
}

// ------------------- fp16 flash attention (4 warps x 32 rows, 4-stage) -------
#define AP16 144
#define AMSZ (64*AP16)                   // 9216 B / matrix
#define ASTG (2*AMSZ)                    // 18432 B / stage (Kh, Vth)
#define A_SMEM (4*ASTG)                  // 73728 B

__device__ __forceinline__ void attn_pf(
    uint32_t sbs, int tid, size_t hb, int t0,
    const __half* kh, const __half* vth)
{
#pragma unroll
    for (int q = 0; q < 8; q++) {
        int id = q * 128 + tid;
        int mat = id >> 9, rem = id & 511, row = rem >> 3, col = rem & 7;
        const __half* g = (mat == 0)
            ? kh  + hb + (size_t)(t0 + row) * DD + col * 8
            : vth + hb + (size_t)row * SQ + t0 + col * 8;
        CPA16(sbs + mat * AMSZ + row * AP16 + col * 16, g);
    }
}

__global__ void __launch_bounds__(128, 2) attn_mma(
    const __half* __restrict__ qh_g, const __half* __restrict__ kh_g,
    const __half* __restrict__ vth, __half* __restrict__ oh_g)
{
    extern __shared__ char sm[];
    uint32_t sb = smem_u32(sm);
    int tid = threadIdx.x, wid = tid >> 5, lane = tid & 31;
    int head = blockIdx.y, m0 = blockIdx.x * 128;
    const size_t hb = (size_t)head * HSZ;
    int r = lane >> 2, c2 = (lane & 3) * 2;
    int l15 = lane & 15, lh = lane >> 4;

    attn_pf(sb,            tid, hb, 0,   kh_g, vth); CPC();
    attn_pf(sb + ASTG,     tid, hb, 64,  kh_g, vth); CPC();
    attn_pf(sb + 2 * ASTG, tid, hb, 128, kh_g, vth); CPC();

    // Q fragments: 2 m-tiles of 16 rows each (warp covers 32 rows)
    uint32_t qh[2][4][4];
    {
        const __half* q0h = qh_g + hb + (size_t)(m0 + wid * 32) * DD;
#pragma unroll
        for (int mt = 0; mt < 2; mt++)
#pragma unroll
            for (int ks = 0; ks < 4; ks++)
#pragma unroll
                for (int j = 0; j < 4; j++) {
                    int rr = mt * 16 + r + (j & 1) * 8;
                    int kk = ks * 16 + c2 + (j >> 1) * 8;
                    qh[mt][ks][j] = *(const uint32_t*)(q0h + rr * DD + kk);
                }
    }

    float oacc[2][8][4] = {};
    float rs[2][2] = {};

    for (int t = 0; t < 64; t++) {
        CPW(2);
        __syncthreads();
        if (t + 3 < 64)
            attn_pf(sb + ((t + 3) & 3) * ASTG, tid, hb, (t + 3) * 64, kh_g, vth);
        CPC();
        uint32_t sbs = sb + (t & 3) * ASTG;

        // per 16-kv slab: S (2 indep m-chains) -> exp -> PV
#pragma unroll
        for (int tt = 0; tt < 4; tt++) {
            float s[2][2][4] = {};
#pragma unroll
            for (int ks = 0; ks < 4; ks++) {
                uint32_t addr = sbs + (tt * 16 + l15) * AP16 + (ks * 16 + 8 * lh) * 2;
                uint32_t h0, h1, h2, h3;
                LDSM4(h0, h1, h2, h3, addr);
                uint32_t b0[2] = {h0, h2}, b1[2] = {h1, h3};
                MMA16816(s[0][0], qh[0][ks], b0);
                MMA16816(s[1][0], qh[1][ks], b0);
                MMA16816(s[0][1], qh[0][ks], b1);
                MMA16816(s[1][1], qh[1][ks], b1);
            }

            uint32_t pa[2][4];
#pragma unroll
            for (int mt = 0; mt < 2; mt++) {
                __half2 hh;
                hh = __floats2half2_rn(s[mt][0][0], s[mt][0][1]); pa[mt][0] = *(uint32_t*)&hh;
                hh = __floats2half2_rn(s[mt][0][2], s[mt][0][3]); pa[mt][1] = *(uint32_t*)&hh;
                hh = __floats2half2_rn(s[mt][1][0], s[mt][1][1]); pa[mt][2] = *(uint32_t*)&hh;
                hh = __floats2half2_rn(s[mt][1][2], s[mt][1][3]); pa[mt][3] = *(uint32_t*)&hh;
                EX2H2(pa[mt][0]); EX2H2(pa[mt][1]); EX2H2(pa[mt][2]); EX2H2(pa[mt][3]);
                float2 f0 = __half22float2(*(__half2*)&pa[mt][0]);
                float2 f1 = __half22float2(*(__half2*)&pa[mt][1]);
                float2 f2 = __half22float2(*(__half2*)&pa[mt][2]);
                float2 f3 = __half22float2(*(__half2*)&pa[mt][3]);
                rs[mt][0] += f0.x + f0.y + f2.x + f2.y;   // rows r
                rs[mt][1] += f1.x + f1.y + f3.x + f3.y;   // rows r+8
            }
#pragma unroll
            for (int jt = 0; jt < 4; jt++) {
                uint32_t addr = sbs + AMSZ + (jt * 16 + l15) * AP16 + (tt * 16 + 8 * lh) * 2;
                uint32_t h0, h1, h2, h3;
                LDSM4(h0, h1, h2, h3, addr);
                uint32_t b0[2] = {h0, h2}, b1[2] = {h1, h3};
                MMA16816(oacc[0][2*jt],   pa[0], b0);
                MMA16816(oacc[1][2*jt],   pa[1], b0);
                MMA16816(oacc[0][2*jt+1], pa[0], b1);
                MMA16816(oacc[1][2*jt+1], pa[1], b1);
            }
        }
    }

    // rowsum reduce across the quad + store
#pragma unroll
    for (int mt = 0; mt < 2; mt++) {
        float r0 = rs[mt][0], r1 = rs[mt][1];
        r0 += __shfl_xor_sync(0xffffffffu, r0, 1);
        r0 += __shfl_xor_sync(0xffffffffu, r0, 2);
        r1 += __shfl_xor_sync(0xffffffffu, r1, 1);
        r1 += __shfl_xor_sync(0xffffffffu, r1, 2);
        float i0 = 1.f / r0, i1 = 1.f / r1;

        size_t rbase = hb + (size_t)(m0 + wid * 32 + mt * 16 + r) * DD;
#pragma unroll
        for (int j = 0; j < 8; j++) {
            __half2 p0 = __floats2half2_rn(oacc[mt][j][0] * i0, oacc[mt][j][1] * i0);
            __half2 p1 = __floats2half2_rn(oacc[mt][j][2] * i1, oacc[mt][j][3] * i1);
            *(uint32_t*)(oh_g + rbase + j * 8 + c2)          = *(uint32_t*)&p0;
            *(uint32_t*)(oh_g + rbase + 8 * DD + j * 8 + c2) = *(uint32_t*)&p1;
        }
    }
}

// ------------------- host -------------------
extern "C" void kernel_launch(void* const* d_in, const int* in_sizes, int n_in,
                              void* d_out, int out_size) {
    const float* Q    = (const float*)d_in[0];
    const float* K    = (const float*)d_in[1];
    const float* V    = (const float*)d_in[2];
    const float* Wqk  = (const float*)d_in[3];
    const float* bqk  = (const float*)d_in[4];
    const float* Wv   = (const float*)d_in[5];
    const float* bv   = (const float*)d_in[6];
    const float* Wout = (const float*)d_in[7];
    const float* bout = (const float*)d_in[8];
    float* out = (float*)d_out;

    float* vf;
    __half *Qh,*Kh,*Vh,*W1h,*W2h,*W3h,*qh,*kh,*vth,*oh;
    cudaGetSymbolAddress((void**)&vf, g_vf);
    cudaGetSymbolAddress((void**)&Qh, g_Qh);   cudaGetSymbolAddress((void**)&Kh, g_Kh);
    cudaGetSymbolAddress((void**)&Vh, g_Vh);
    cudaGetSymbolAddress((void**)&W1h, g_W1h); cudaGetSymbolAddress((void**)&W2h, g_W2h);
    cudaGetSymbolAddress((void**)&W3h, g_W3h);
    cudaGetSymbolAddress((void**)&qh, g_qh);   cudaGetSymbolAddress((void**)&kh, g_kh);
    cudaGetSymbolAddress((void**)&vth, g_vth); cudaGetSymbolAddress((void**)&oh, g_oh);
    __half* vf16 = (__half*)vf;

    cudaFuncSetAttribute(gemm_mma, cudaFuncAttributeMaxDynamicSharedMemorySize, G_SMEM);
    cudaFuncSetAttribute(attn_mma, cudaFuncAttributeMaxDynamicSharedMemorySize, A_SMEM);

    const int TB = 256;
    cvt1x3<<<dim3(TOT/4/TB, 3), TB>>>((const float4*)Q, (uint2*)Qh,
                                      (const float4*)K, (uint2*)Kh,
                                      (const float4*)V, (uint2*)Vh);
    cvt1x3<<<dim3(EE*EE/4/TB, 3), TB>>>((const float4*)Wqk,  (uint2*)W1h,
                                        (const float4*)Wv,   (uint2*)W2h,
                                        (const float4*)Wout, (uint2*)W3h);

    const float QSC = 0.125f * 1.4426950408889634f;
    GemmArgs gp = {};
    gp.Ah[0]=Qh; gp.Wh[0]=W1h; gp.bias[0]=bqk; gp.Ch[0]=qh;   gp.scale[0]=QSC; gp.mode[0]=2;
    gp.Ah[1]=Kh; gp.Wh[1]=W1h; gp.bias[1]=bqk; gp.Ch[1]=kh;   gp.scale[1]=1.f; gp.mode[1]=2;
    gp.Ah[2]=Vh; gp.Wh[2]=W2h; gp.bias[2]=bv;  gp.Ch[2]=vf16; gp.scale[2]=1.f; gp.mode[2]=2;
    gemm_mma<<<dim3(EE/128, SQ/128, 3), TB, G_SMEM>>>(gp);

    vtrans_h<<<dim3(SQ/32, DD/32, HH), dim3(32,32)>>>(vf16, vth);

    attn_mma<<<dim3(SQ/128, HH), 128, A_SMEM>>>(qh, kh, vth, oh);

    GemmArgs go = {};
    go.Ah[0]=oh; go.Wh[0]=W3h; go.bias[0]=bout; go.Cf[0]=out; go.scale[0]=1.f; go.mode[0]=0;
    gemm_mma<<<dim3(EE/128, SQ/128, 1), TB, G_SMEM>>>(go);
}

// round 15
// speedup vs baseline: 2.8650x; 1.0581x over previous
#include <cuda_runtime.h>
#include <cuda_fp16.h>
#include <cstdint>

#define SQ 4096
#define EE 512
#define HH 8
#define DD 64
#define HSZ (SQ*DD)
#define TOT (SQ*EE)

// ------------------- global scratch -------------------
__device__ float g_vf[TOT];   // reused as fp16 buffer for V projection output
__device__ __half g_Qh[TOT], g_Kh[TOT], g_Vh[TOT];
__device__ __half g_W1h[EE*EE], g_W2h[EE*EE], g_W3h[EE*EE];
__device__ __half g_qh[TOT], g_kh[TOT], g_vth[TOT], g_oh[TOT];

// ------------------- helpers -------------------
__device__ __forceinline__ uint32_t smem_u32(const void* p) {
    uint32_t a;
    asm("{ .reg .u64 t; cvta.to.shared.u64 t, %1; cvt.u32.u64 %0, t; }" : "=r"(a) : "l"(p));
    return a;
}
#define LDSM4(R0,R1,R2,R3,ADDR) \
    asm volatile("ldmatrix.sync.aligned.m8n8.x4.shared.b16 {%0,%1,%2,%3}, [%4];" \
        : "=r"(R0),"=r"(R1),"=r"(R2),"=r"(R3) : "r"(ADDR))
#define MMA16816(C,A,B) \
    asm volatile("mma.sync.aligned.m16n8k16.row.col.f32.f16.f16.f32 " \
        "{%0,%1,%2,%3},{%4,%5,%6,%7},{%8,%9},{%0,%1,%2,%3};" \
        : "+f"((C)[0]),"+f"((C)[1]),"+f"((C)[2]),"+f"((C)[3]) \
        : "r"((A)[0]),"r"((A)[1]),"r"((A)[2]),"r"((A)[3]),"r"((B)[0]),"r"((B)[1]))
#define MMA16816H(C0,C1,A,B) \
    asm volatile("mma.sync.aligned.m16n8k16.row.col.f16.f16.f16.f16 " \
        "{%0,%1},{%2,%3,%4,%5},{%6,%7},{%0,%1};" \
        : "+r"(C0),"+r"(C1) \
        : "r"((A)[0]),"r"((A)[1]),"r"((A)[2]),"r"((A)[3]),"r"((B)[0]),"r"((B)[1]))
#define CPA16(DST,SRC) \
    asm volatile("cp.async.cg.shared.global [%0], [%1], 16;" :: "r"(DST), "l"(SRC) : "memory")
#define CPC() asm volatile("cp.async.commit_group;" ::: "memory")
#define CPW(N) asm volatile("cp.async.wait_group %0;" :: "n"(N) : "memory")
#define EX2H2(D) asm("ex2.approx.f16x2 %0, %0;" : "+r"(D))

// ------------------- fp32 -> fp16 convert (3 tensors / launch) --------------
__global__ void cvt1x3(const float4* __restrict__ x0, uint2* __restrict__ h0,
                       const float4* __restrict__ x1, uint2* __restrict__ h1,
                       const float4* __restrict__ x2, uint2* __restrict__ h2) {
    const float4* x = blockIdx.y == 0 ? x0 : blockIdx.y == 1 ? x1 : x2;
    uint2* hi = blockIdx.y == 0 ? h0 : blockIdx.y == 1 ? h1 : h2;
    int i = blockIdx.x * blockDim.x + threadIdx.x;
    float4 v = x[i];
    __half2 a01 = __floats2half2_rn(v.x, v.y);
    __half2 a23 = __floats2half2_rn(v.z, v.w);
    uint2 hv;
    hv.x = *(uint32_t*)&a01; hv.y = *(uint32_t*)&a23;
    hi[i] = hv;
}

// per-head V transpose, 2x2-block half2 (4B loads + 4B stores), layout-correct
__global__ void vtrans_h2(const __half2* __restrict__ vf2, __half2* __restrict__ vt2) {
    __shared__ __half2 tile[64][33];
    int h = blockIdx.z, t0 = blockIdx.x * 64;
    int tid = threadIdx.x;
    const __half2* src = vf2 + (size_t)h * (HSZ / 2) + (size_t)t0 * 32;
#pragma unroll
    for (int it = 0; it < 4; it++) {
        int idx = it * 256 + tid;
        int x = idx & 31, y = idx >> 5;                 // x: d-pair, y: token-pair
        __half2 a = src[(2 * y) * 32 + x];
        __half2 b = src[(2 * y + 1) * 32 + x];
        tile[2 * x][y]     = __halves2half2(__low2half(a),  __low2half(b));
        tile[2 * x + 1][y] = __halves2half2(__high2half(a), __high2half(b));
    }
    __syncthreads();
    __half2* dst = vt2 + (size_t)h * (HSZ / 2) + t0 / 2;
#pragma unroll
    for (int it = 0; it < 8; it++) {
        int idx = it * 256 + tid;
        int d = idx >> 5, y = idx & 31;
        dst[(size_t)d * (SQ / 2) + y] = tile[d][y];
    }
}

// ------------------- fp16 GEMM (K-chunk 16, 4-stage, race-free) --------------
#define GP16 48
#define GMSZ (128*GP16)                  // 6144 B / matrix
#define GSTG (2*GMSZ)                    // 12288 B / stage (A, W)
#define G_SMEM (4*GSTG)                  // 49152 B

struct GemmArgs {
    const __half *Ah[3], *Wh[3];
    const float* bias[3];
    float* Cf[3];
    __half *Ch[3];
    float scale[3];
    int mode[3];   // 0: fp32 out, 2: fp16 out
};

__device__ __forceinline__ void gemm_pf(
    uint32_t sbs, int tid, int m0, int n0, int ch,
    const __half* Ah, const __half* Wh)
{
#pragma unroll
    for (int q = 0; q < 2; q++) {
        int id = q * 256 + tid;
        int mat = id >> 8, rem = id & 255, row = rem >> 1, col = rem & 1;
        const __half* g = (mat == 0 ? Ah : Wh)
            + (size_t)((mat == 0 ? m0 : n0) + row) * EE + ch * 16 + col * 8;
        CPA16(sbs + mat * GMSZ + row * GP16 + col * 16, g);
    }
}

__global__ void __launch_bounds__(256, 2) gemm_mma(GemmArgs ga)
{
    extern __shared__ char sm[];
    uint32_t sb = smem_u32(sm);
    int tid = threadIdx.x, wid = tid >> 5, lane = tid & 31;
    int wm = wid & 3, wn = wid >> 2;
    int m0 = blockIdx.y * 128, n0 = blockIdx.x * 128;
    int z = blockIdx.z;
    int l15 = lane & 15, lh = lane >> 4;

    const __half *Ah = ga.Ah[z], *Wh = ga.Wh[z];
    const float* bias = ga.bias[z];
    float* Cf = ga.Cf[z];
    __half* Chi = ga.Ch[z];
    float scale = ga.scale[z];
    int mode = ga.mode[z];

    float acc[2][8][4] = {};

    gemm_pf(sb,            tid, m0, n0, 0, Ah, Wh); CPC();
    gemm_pf(sb + GSTG,     tid, m0, n0, 1, Ah, Wh); CPC();
    gemm_pf(sb + 2 * GSTG, tid, m0, n0, 2, Ah, Wh); CPC();

    for (int ch = 0; ch < 32; ch++) {
        CPW(2);
        __syncthreads();
        if (ch + 3 < 32)
            gemm_pf(sb + ((ch + 3) & 3) * GSTG, tid, m0, n0, ch + 3, Ah, Wh);
        CPC();
        uint32_t sbs = sb + (ch & 3) * GSTG;

        uint32_t ah[2][4];
#pragma unroll
        for (int mt = 0; mt < 2; mt++) {
            uint32_t addr = sbs + (wm * 32 + mt * 16 + l15) * GP16 + lh * 16;
            LDSM4(ah[mt][0], ah[mt][1], ah[mt][2], ah[mt][3], addr);
        }
#pragma unroll
        for (int jt = 0; jt < 4; jt++) {
            uint32_t addr = sbs + GMSZ + (wn * 64 + jt * 16 + l15) * GP16 + lh * 16;
            uint32_t h0, h1, h2, h3;
            LDSM4(h0, h1, h2, h3, addr);
            uint32_t b0[2] = {h0, h2}, b1[2] = {h1, h3};
#pragma unroll
            for (int mt = 0; mt < 2; mt++) {
                MMA16816(acc[mt][2*jt],   ah[mt], b0);
                MMA16816(acc[mt][2*jt+1], ah[mt], b1);
            }
        }
    }

    int r = lane >> 2, c2 = (lane & 3) * 2;
#pragma unroll
    for (int mt = 0; mt < 2; mt++) {
        size_t rbase = (size_t)(m0 + wm * 32 + mt * 16 + r) * EE + n0 + wn * 64;
#pragma unroll
        for (int j = 0; j < 8; j++) {
            float b0 = __ldg(bias + n0 + wn * 64 + j * 8 + c2);
            float b1 = __ldg(bias + n0 + wn * 64 + j * 8 + c2 + 1);
            float y00 = (acc[mt][j][0] + b0) * scale, y01 = (acc[mt][j][1] + b1) * scale;
            float y10 = (acc[mt][j][2] + b0) * scale, y11 = (acc[mt][j][3] + b1) * scale;
            if (mode == 0) {
                *(float2*)(Cf + rbase + j * 8 + c2)          = make_float2(y00, y01);
                *(float2*)(Cf + rbase + 8 * EE + j * 8 + c2) = make_float2(y10, y11);
            } else {
                __half2 p0 = __floats2half2_rn(y00, y01);
                __half2 p1 = __floats2half2_rn(y10, y11);
                *(uint32_t*)(Chi + rbase + j * 8 + c2)          = *(uint32_t*)&p0;
                *(uint32_t*)(Chi + rbase + 8 * EE + j * 8 + c2) = *(uint32_t*)&p1;
            }
        }
    }
}

// ------------------- fp16 flash attention (f16-accum S, 4-stage) -------------
#define AP16 144
#define AMSZ (64*AP16)                   // 9216 B / matrix
#define ASTG (2*AMSZ)                    // 18432 B / stage (Kh, Vth)
#define A_SMEM (4*ASTG)                  // 73728 B

__device__ __forceinline__ void attn_pf(
    uint32_t sbs, int tid, size_t hb, int t0,
    const __half* kh, const __half* vth)
{
#pragma unroll
    for (int q = 0; q < 8; q++) {
        int id = q * 128 + tid;
        int mat = id >> 9, rem = id & 511, row = rem >> 3, col = rem & 7;
        const __half* g = (mat == 0)
            ? kh  + hb + (size_t)(t0 + row) * DD + col * 8
            : vth + hb + (size_t)row * SQ + t0 + col * 8;
        CPA16(sbs + mat * AMSZ + row * AP16 + col * 16, g);
    }
}

__global__ void __launch_bounds__(128, 2) attn_mma(
    const __half* __restrict__ qh_g, const __half* __restrict__ kh_g,
    const __half* __restrict__ vth, __half* __restrict__ oh_g)
{
    extern __shared__ char sm[];
    uint32_t sb = smem_u32(sm);
    int tid = threadIdx.x, wid = tid >> 5, lane = tid & 31;
    int head = blockIdx.y, m0 = blockIdx.x * 128;
    const size_t hb = (size_t)head * HSZ;
    int r = lane >> 2, c2 = (lane & 3) * 2;
    int l15 = lane & 15, lh = lane >> 4;

    attn_pf(sb,            tid, hb, 0,   kh_g, vth); CPC();
    attn_pf(sb + ASTG,     tid, hb, 64,  kh_g, vth); CPC();
    attn_pf(sb + 2 * ASTG, tid, hb, 128, kh_g, vth); CPC();

    // Q fragments: 2 m-tiles of 16 rows (warp covers 32 rows); pre-scaled by 0.125*log2e
    uint32_t qh[2][4][4];
    {
        const __half* q0h = qh_g + hb + (size_t)(m0 + wid * 32) * DD;
#pragma unroll
        for (int mt = 0; mt < 2; mt++)
#pragma unroll
            for (int ks = 0; ks < 4; ks++)
#pragma unroll
                for (int j = 0; j < 4; j++) {
                    int rr = mt * 16 + r + (j & 1) * 8;
                    int kk = ks * 16 + c2 + (j >> 1) * 8;
                    qh[mt][ks][j] = *(const uint32_t*)(q0h + rr * DD + kk);
                }
    }

    float oacc[2][8][4] = {};
    float rs[2][2] = {};

    for (int t = 0; t < 64; t++) {
        CPW(2);
        __syncthreads();
        if (t + 3 < 64)
            attn_pf(sb + ((t + 3) & 3) * ASTG, tid, hb, (t + 3) * 64, kh_g, vth);
        CPC();
        uint32_t sbs = sb + (t & 3) * ASTG;

        // per 16-kv slab: S (f16 accum -> IS the P A-fragment) -> exp in place -> PV
#pragma unroll
        for (int tt = 0; tt < 4; tt++) {
            uint32_t pa[2][4] = {{0u,0u,0u,0u},{0u,0u,0u,0u}};
#pragma unroll
            for (int ks = 0; ks < 4; ks++) {
                uint32_t addr = sbs + (tt * 16 + l15) * AP16 + (ks * 16 + 8 * lh) * 2;
                uint32_t h0, h1, h2, h3;
                LDSM4(h0, h1, h2, h3, addr);
                uint32_t b0[2] = {h0, h2}, b1[2] = {h1, h3};
                MMA16816H(pa[0][0], pa[0][1], qh[0][ks], b0);
                MMA16816H(pa[1][0], pa[1][1], qh[1][ks], b0);
                MMA16816H(pa[0][2], pa[0][3], qh[0][ks], b1);
                MMA16816H(pa[1][2], pa[1][3], qh[1][ks], b1);
            }
#pragma unroll
            for (int mt = 0; mt < 2; mt++) {
                EX2H2(pa[mt][0]); EX2H2(pa[mt][1]); EX2H2(pa[mt][2]); EX2H2(pa[mt][3]);
                float2 f0 = __half22float2(*(__half2*)&pa[mt][0]);
                float2 f1 = __half22float2(*(__half2*)&pa[mt][1]);
                float2 f2 = __half22float2(*(__half2*)&pa[mt][2]);
                float2 f3 = __half22float2(*(__half2*)&pa[mt][3]);
                rs[mt][0] += f0.x + f0.y + f2.x + f2.y;   // rows r
                rs[mt][1] += f1.x + f1.y + f3.x + f3.y;   // rows r+8
            }
#pragma unroll
            for (int jt = 0; jt < 4; jt++) {
                uint32_t addr = sbs + AMSZ + (jt * 16 + l15) * AP16 + (tt * 16 + 8 * lh) * 2;
                uint32_t h0, h1, h2, h3;
                LDSM4(h0, h1, h2, h3, addr);
                uint32_t b0[2] = {h0, h2}, b1[2] = {h1, h3};
                MMA16816(oacc[0][2*jt],   pa[0], b0);
                MMA16816(oacc[1][2*jt],   pa[1], b0);
                MMA16816(oacc[0][2*jt+1], pa[0], b1);
                MMA16816(oacc[1][2*jt+1], pa[1], b1);
            }
        }
    }

    // rowsum reduce across the quad + store
#pragma unroll
    for (int mt = 0; mt < 2; mt++) {
        float r0 = rs[mt][0], r1 = rs[mt][1];
        r0 += __shfl_xor_sync(0xffffffffu, r0, 1);
        r0 += __shfl_xor_sync(0xffffffffu, r0, 2);
        r1 += __shfl_xor_sync(0xffffffffu, r1, 1);
        r1 += __shfl_xor_sync(0xffffffffu, r1, 2);
        float i0 = 1.f / r0, i1 = 1.f / r1;

        size_t rbase = hb + (size_t)(m0 + wid * 32 + mt * 16 + r) * DD;
#pragma unroll
        for (int j = 0; j < 8; j++) {
            __half2 p0 = __floats2half2_rn(oacc[mt][j][0] * i0, oacc[mt][j][1] * i0);
            __half2 p1 = __floats2half2_rn(oacc[mt][j][2] * i1, oacc[mt][j][3] * i1);
            *(uint32_t*)(oh_g + rbase + j * 8 + c2)          = *(uint32_t*)&p0;
            *(uint32_t*)(oh_g + rbase + 8 * DD + j * 8 + c2) = *(uint32_t*)&p1;
        }
    }
}

// ------------------- host -------------------
extern "C" void kernel_launch(void* const* d_in, const int* in_sizes, int n_in,
                              void* d_out, int out_size) {
    const float* Q    = (const float*)d_in[0];
    const float* K    = (const float*)d_in[1];
    const float* V    = (const float*)d_in[2];
    const float* Wqk  = (const float*)d_in[3];
    const float* bqk  = (const float*)d_in[4];
    const float* Wv   = (const float*)d_in[5];
    const float* bv   = (const float*)d_in[6];
    const float* Wout = (const float*)d_in[7];
    const float* bout = (const float*)d_in[8];
    float* out = (float*)d_out;

    float* vf;
    __half *Qh,*Kh,*Vh,*W1h,*W2h,*W3h,*qh,*kh,*vth,*oh;
    cudaGetSymbolAddress((void**)&vf, g_vf);
    cudaGetSymbolAddress((void**)&Qh, g_Qh);   cudaGetSymbolAddress((void**)&Kh, g_Kh);
    cudaGetSymbolAddress((void**)&Vh, g_Vh);
    cudaGetSymbolAddress((void**)&W1h, g_W1h); cudaGetSymbolAddress((void**)&W2h, g_W2h);
    cudaGetSymbolAddress((void**)&W3h, g_W3h);
    cudaGetSymbolAddress((void**)&qh, g_qh);   cudaGetSymbolAddress((void**)&kh, g_kh);
    cudaGetSymbolAddress((void**)&vth, g_vth); cudaGetSymbolAddress((void**)&oh, g_oh);
    __half* vf16 = (__half*)vf;

    cudaFuncSetAttribute(gemm_mma, cudaFuncAttributeMaxDynamicSharedMemorySize, G_SMEM);
    cudaFuncSetAttribute(attn_mma, cudaFuncAttributeMaxDynamicSharedMemorySize, A_SMEM);

    const int TB = 256;
    cvt1x3<<<dim3(TOT/4/TB, 3), TB>>>((const float4*)Q, (uint2*)Qh,
                                      (const float4*)K, (uint2*)Kh,
                                      (const float4*)V, (uint2*)Vh);
    cvt1x3<<<dim3(EE*EE/4/TB, 3), TB>>>((const float4*)Wqk,  (uint2*)W1h,
                                        (const float4*)Wv,   (uint2*)W2h,
                                        (const float4*)Wout, (uint2*)W3h);

    const float QSC = 0.125f * 1.4426950408889634f;
    GemmArgs gp = {};
    gp.Ah[0]=Qh; gp.Wh[0]=W1h; gp.bias[0]=bqk; gp.Ch[0]=qh;   gp.scale[0]=QSC; gp.mode[0]=2;
    gp.Ah[1]=Kh; gp.Wh[1]=W1h; gp.bias[1]=bqk; gp.Ch[1]=kh;   gp.scale[1]=1.f; gp.mode[1]=2;
    gp.Ah[2]=Vh; gp.Wh[2]=W2h; gp.bias[2]=bv;  gp.Ch[2]=vf16; gp.scale[2]=1.f; gp.mode[2]=2;
    gemm_mma<<<dim3(EE/128, SQ/128, 3), TB, G_SMEM>>>(gp);

    vtrans_h2<<<dim3(SQ/64, 1, HH), 256>>>((const __half2*)vf16, (__half2*)vth);

    attn_mma<<<dim3(SQ/128, HH), 128, A_SMEM>>>(qh, kh, vth, oh);

    GemmArgs go = {};
    go.Ah[0]=oh; go.Wh[0]=W3h; go.bias[0]=bout; go.Cf[0]=out; go.scale[0]=1.f; go.mode[0]=0;
    gemm_mma<<<dim3(EE/128, SQ/128, 1), TB, G_SMEM>>>(go);
}

// round 16
// speedup vs baseline: 2.9918x; 1.0443x over previous
#include <cuda_runtime.h>
#include <cuda_fp16.h>
#include <cstdint>

#define SQ 4096
#define EE 512
#define HH 8
#define DD 64
#define HSZ (SQ*DD)
#define TOT (SQ*EE)

// ------------------- global scratch -------------------
__device__ float g_vf[TOT];   // reused as fp16 buffer for V projection output
__device__ __half g_Qh[TOT], g_Kh[TOT], g_Vh[TOT];
__device__ __half g_W1h[EE*EE], g_W2h[EE*EE], g_W3h[EE*EE];
__device__ __half g_qh[TOT], g_kh[TOT], g_oh[TOT];

// ------------------- helpers -------------------
__device__ __forceinline__ uint32_t smem_u32(const void* p) {
    uint32_t a;
    asm("{ .reg .u64 t; cvta.to.shared.u64 t, %1; cvt.u32.u64 %0, t; }" : "=r"(a) : "l"(p));
    return a;
}
#define LDSM4(R0,R1,R2,R3,ADDR) \
    asm volatile("ldmatrix.sync.aligned.m8n8.x4.shared.b16 {%0,%1,%2,%3}, [%4];" \
        : "=r"(R0),"=r"(R1),"=r"(R2),"=r"(R3) : "r"(ADDR))
#define LDSM4T(R0,R1,R2,R3,ADDR) \
    asm volatile("ldmatrix.sync.aligned.m8n8.x4.trans.shared.b16 {%0,%1,%2,%3}, [%4];" \
        : "=r"(R0),"=r"(R1),"=r"(R2),"=r"(R3) : "r"(ADDR))
#define MMA16816(C,A,B) \
    asm volatile("mma.sync.aligned.m16n8k16.row.col.f32.f16.f16.f32 " \
        "{%0,%1,%2,%3},{%4,%5,%6,%7},{%8,%9},{%0,%1,%2,%3};" \
        : "+f"((C)[0]),"+f"((C)[1]),"+f"((C)[2]),"+f"((C)[3]) \
        : "r"((A)[0]),"r"((A)[1]),"r"((A)[2]),"r"((A)[3]),"r"((B)[0]),"r"((B)[1]))
#define MMA16816H(C0,C1,A,B) \
    asm volatile("mma.sync.aligned.m16n8k16.row.col.f16.f16.f16.f16 " \
        "{%0,%1},{%2,%3,%4,%5},{%6,%7},{%0,%1};" \
        : "+r"(C0),"+r"(C1) \
        : "r"((A)[0]),"r"((A)[1]),"r"((A)[2]),"r"((A)[3]),"r"((B)[0]),"r"((B)[1]))
#define CPA16(DST,SRC) \
    asm volatile("cp.async.cg.shared.global [%0], [%1], 16;" :: "r"(DST), "l"(SRC) : "memory")
#define CPC() asm volatile("cp.async.commit_group;" ::: "memory")
#define CPW(N) asm volatile("cp.async.wait_group %0;" :: "n"(N) : "memory")
#define EX2H2(D) asm("ex2.approx.f16x2 %0, %0;" : "+r"(D))

// ------------------- fp32 -> fp16 convert (3 tensors / launch) --------------
__global__ void cvt1x3(const float4* __restrict__ x0, uint2* __restrict__ h0,
                       const float4* __restrict__ x1, uint2* __restrict__ h1,
                       const float4* __restrict__ x2, uint2* __restrict__ h2) {
    const float4* x = blockIdx.y == 0 ? x0 : blockIdx.y == 1 ? x1 : x2;
    uint2* hi = blockIdx.y == 0 ? h0 : blockIdx.y == 1 ? h1 : h2;
    int i = blockIdx.x * blockDim.x + threadIdx.x;
    float4 v = x[i];
    __half2 a01 = __floats2half2_rn(v.x, v.y);
    __half2 a23 = __floats2half2_rn(v.z, v.w);
    uint2 hv;
    hv.x = *(uint32_t*)&a01; hv.y = *(uint32_t*)&a23;
    hi[i] = hv;
}

// ------------------- fp16 GEMM (K-chunk 16, 4-stage, race-free) --------------
#define GP16 48
#define GMSZ (128*GP16)                  // 6144 B / matrix
#define GSTG (2*GMSZ)                    // 12288 B / stage (A, W)
#define G_SMEM (4*GSTG)                  // 49152 B

struct GemmArgs {
    const __half *Ah[3], *Wh[3];
    const float* bias[3];
    float* Cf[3];
    __half *Ch[3];
    float scale[3];
    int mode[3];   // 0: fp32 out, 2: fp16 out
};

__device__ __forceinline__ void gemm_pf(
    uint32_t sbs, int tid, int m0, int n0, int ch,
    const __half* Ah, const __half* Wh)
{
#pragma unroll
    for (int q = 0; q < 2; q++) {
        int id = q * 256 + tid;
        int mat = id >> 8, rem = id & 255, row = rem >> 1, col = rem & 1;
        const __half* g = (mat == 0 ? Ah : Wh)
            + (size_t)((mat == 0 ? m0 : n0) + row) * EE + ch * 16 + col * 8;
        CPA16(sbs + mat * GMSZ + row * GP16 + col * 16, g);
    }
}

__global__ void __launch_bounds__(256, 2) gemm_mma(GemmArgs ga)
{
    extern __shared__ char sm[];
    uint32_t sb = smem_u32(sm);
    int tid = threadIdx.x, wid = tid >> 5, lane = tid & 31;
    int wm = wid & 3, wn = wid >> 2;
    int m0 = blockIdx.y * 128, n0 = blockIdx.x * 128;
    int z = blockIdx.z;
    int l15 = lane & 15, lh = lane >> 4;

    const __half *Ah = ga.Ah[z], *Wh = ga.Wh[z];
    const float* bias = ga.bias[z];
    float* Cf = ga.Cf[z];
    __half* Chi = ga.Ch[z];
    float scale = ga.scale[z];
    int mode = ga.mode[z];

    float acc[2][8][4] = {};

    gemm_pf(sb,            tid, m0, n0, 0, Ah, Wh); CPC();
    gemm_pf(sb + GSTG,     tid, m0, n0, 1, Ah, Wh); CPC();
    gemm_pf(sb + 2 * GSTG, tid, m0, n0, 2, Ah, Wh); CPC();

    for (int ch = 0; ch < 32; ch++) {
        CPW(2);
        __syncthreads();
        if (ch + 3 < 32)
            gemm_pf(sb + ((ch + 3) & 3) * GSTG, tid, m0, n0, ch + 3, Ah, Wh);
        CPC();
        uint32_t sbs = sb + (ch & 3) * GSTG;

        uint32_t ah[2][4];
#pragma unroll
        for (int mt = 0; mt < 2; mt++) {
            uint32_t addr = sbs + (wm * 32 + mt * 16 + l15) * GP16 + lh * 16;
            LDSM4(ah[mt][0], ah[mt][1], ah[mt][2], ah[mt][3], addr);
        }
#pragma unroll
        for (int jt = 0; jt < 4; jt++) {
            uint32_t addr = sbs + GMSZ + (wn * 64 + jt * 16 + l15) * GP16 + lh * 16;
            uint32_t h0, h1, h2, h3;
            LDSM4(h0, h1, h2, h3, addr);
            uint32_t b0[2] = {h0, h2}, b1[2] = {h1, h3};
#pragma unroll
            for (int mt = 0; mt < 2; mt++) {
                MMA16816(acc[mt][2*jt],   ah[mt], b0);
                MMA16816(acc[mt][2*jt+1], ah[mt], b1);
            }
        }
    }

    int r = lane >> 2, c2 = (lane & 3) * 2;
#pragma unroll
    for (int mt = 0; mt < 2; mt++) {
        size_t rbase = (size_t)(m0 + wm * 32 + mt * 16 + r) * EE + n0 + wn * 64;
#pragma unroll
        for (int j = 0; j < 8; j++) {
            float b0 = __ldg(bias + n0 + wn * 64 + j * 8 + c2);
            float b1 = __ldg(bias + n0 + wn * 64 + j * 8 + c2 + 1);
            float y00 = (acc[mt][j][0] + b0) * scale, y01 = (acc[mt][j][1] + b1) * scale;
            float y10 = (acc[mt][j][2] + b0) * scale, y11 = (acc[mt][j][3] + b1) * scale;
            if (mode == 0) {
                *(float2*)(Cf + rbase + j * 8 + c2)          = make_float2(y00, y01);
                *(float2*)(Cf + rbase + 8 * EE + j * 8 + c2) = make_float2(y10, y11);
            } else {
                __half2 p0 = __floats2half2_rn(y00, y01);
                __half2 p1 = __floats2half2_rn(y10, y11);
                *(uint32_t*)(Chi + rbase + j * 8 + c2)          = *(uint32_t*)&p0;
                *(uint32_t*)(Chi + rbase + 8 * EE + j * 8 + c2) = *(uint32_t*)&p1;
            }
        }
    }
}

// ------- fp16 flash attention (trans-ldmatrix V, rowsum-by-MMA, 4-stage) -----
#define AP16 144
#define AMSZ (64*AP16)                   // 9216 B / matrix
#define ASTG (2*AMSZ)                    // 18432 B / stage (K, V — both row=token)
#define A_SMEM (4*ASTG)                  // 73728 B

__device__ __forceinline__ void attn_pf(
    uint32_t sbs, int tid, size_t hb, int t0,
    const __half* kh, const __half* vh)
{
#pragma unroll
    for (int q = 0; q < 8; q++) {
        int id = q * 128 + tid;
        int mat = id >> 9, rem = id & 511, row = rem >> 3, col = rem & 7;
        const __half* g = (mat == 0 ? kh : vh) + hb + (size_t)(t0 + row) * DD + col * 8;
        CPA16(sbs + mat * AMSZ + row * AP16 + col * 16, g);
    }
}

__global__ void __launch_bounds__(128, 2) attn_mma(
    const __half* __restrict__ qh_g, const __half* __restrict__ kh_g,
    const __half* __restrict__ vh_g, __half* __restrict__ oh_g)
{
    extern __shared__ char sm[];
    uint32_t sb = smem_u32(sm);
    int tid = threadIdx.x, wid = tid >> 5, lane = tid & 31;
    int head = blockIdx.y, m0 = blockIdx.x * 128;
    const size_t hb = (size_t)head * HSZ;
    int r = lane >> 2, c2 = (lane & 3) * 2;
    int l15 = lane & 15, lh = lane >> 4;
    // trans-ldmatrix addressing for V (row-major [kv][d]):
    int g8 = lane >> 3, w8 = lane & 7;
    int vro = ((g8 >> 1) & 1) * 8 + w8;   // kv within slab
    int vco = (g8 & 1) * 8;               // d octet within jt tile

    attn_pf(sb,            tid, hb, 0,   kh_g, vh_g); CPC();
    attn_pf(sb + ASTG,     tid, hb, 64,  kh_g, vh_g); CPC();
    attn_pf(sb + 2 * ASTG, tid, hb, 128, kh_g, vh_g); CPC();

    // Q fragments: 2 m-tiles of 16 rows (warp covers 32 rows); pre-scaled by 0.125*log2e
    uint32_t qh[2][4][4];
    {
        const __half* q0h = qh_g + hb + (size_t)(m0 + wid * 32) * DD;
#pragma unroll
        for (int mt = 0; mt < 2; mt++)
#pragma unroll
            for (int ks = 0; ks < 4; ks++)
#pragma unroll
                for (int j = 0; j < 4; j++) {
                    int rr = mt * 16 + r + (j & 1) * 8;
                    int kk = ks * 16 + c2 + (j >> 1) * 8;
                    qh[mt][ks][j] = *(const uint32_t*)(q0h + rr * DD + kk);
                }
    }

    float oacc[2][8][4] = {};
    float racc[2][4] = {};
    const uint32_t bones[2] = {0x3C003C00u, 0x3C003C00u};  // fp16 1.0 x2, both k-octets

    for (int t = 0; t < 64; t++) {
        CPW(2);
        __syncthreads();
        if (t + 3 < 64)
            attn_pf(sb + ((t + 3) & 3) * ASTG, tid, hb, (t + 3) * 64, kh_g, vh_g);
        CPC();
        uint32_t sbs = sb + (t & 3) * ASTG;

        // per 16-kv slab: S (f16 accum == P A-frag) -> exp in place -> rowsum MMA + PV
#pragma unroll
        for (int tt = 0; tt < 4; tt++) {
            uint32_t pa[2][4] = {{0u,0u,0u,0u},{0u,0u,0u,0u}};
#pragma unroll
            for (int ks = 0; ks < 4; ks++) {
                uint32_t addr = sbs + (tt * 16 + l15) * AP16 + (ks * 16 + 8 * lh) * 2;
                uint32_t h0, h1, h2, h3;
                LDSM4(h0, h1, h2, h3, addr);
                uint32_t b0[2] = {h0, h2}, b1[2] = {h1, h3};
                MMA16816H(pa[0][0], pa[0][1], qh[0][ks], b0);
                MMA16816H(pa[1][0], pa[1][1], qh[1][ks], b0);
                MMA16816H(pa[0][2], pa[0][3], qh[0][ks], b1);
                MMA16816H(pa[1][2], pa[1][3], qh[1][ks], b1);
            }
            EX2H2(pa[0][0]); EX2H2(pa[0][1]); EX2H2(pa[0][2]); EX2H2(pa[0][3]);
            EX2H2(pa[1][0]); EX2H2(pa[1][1]); EX2H2(pa[1][2]); EX2H2(pa[1][3]);
            MMA16816(racc[0], pa[0], bones);   // exact fp32 rowsum accumulation
            MMA16816(racc[1], pa[1], bones);
#pragma unroll
            for (int jt = 0; jt < 4; jt++) {
                uint32_t addr = sbs + AMSZ + (tt * 16 + vro) * AP16 + (jt * 16 + vco) * 2;
                uint32_t h0, h1, h2, h3;
                LDSM4T(h0, h1, h2, h3, addr);
                uint32_t b0[2] = {h0, h2}, b1[2] = {h1, h3};
                MMA16816(oacc[0][2*jt],   pa[0], b0);
                MMA16816(oacc[1][2*jt],   pa[1], b0);
                MMA16816(oacc[0][2*jt+1], pa[0], b1);
                MMA16816(oacc[1][2*jt+1], pa[1], b1);
            }
        }
    }

    // normalize + store (racc[mt][0] = rowsum rows r; [2] = rows r+8; no shuffles)
#pragma unroll
    for (int mt = 0; mt < 2; mt++) {
        float i0 = 1.f / racc[mt][0], i1 = 1.f / racc[mt][2];
        size_t rbase = hb + (size_t)(m0 + wid * 32 + mt * 16 + r) * DD;
#pragma unroll
        for (int j = 0; j < 8; j++) {
            __half2 p0 = __floats2half2_rn(oacc[mt][j][0] * i0, oacc[mt][j][1] * i0);
            __half2 p1 = __floats2half2_rn(oacc[mt][j][2] * i1, oacc[mt][j][3] * i1);
            *(uint32_t*)(oh_g + rbase + j * 8 + c2)          = *(uint32_t*)&p0;
            *(uint32_t*)(oh_g + rbase + 8 * DD + j * 8 + c2) = *(uint32_t*)&p1;
        }
    }
}

// ------------------- host -------------------
extern "C" void kernel_launch(void* const* d_in, const int* in_sizes, int n_in,
                              void* d_out, int out_size) {
    const float* Q    = (const float*)d_in[0];
    const float* K    = (const float*)d_in[1];
    const float* V    = (const float*)d_in[2];
    const float* Wqk  = (const float*)d_in[3];
    const float* bqk  = (const float*)d_in[4];
    const float* Wv   = (const float*)d_in[5];
    const float* bv   = (const float*)d_in[6];
    const float* Wout = (const float*)d_in[7];
    const float* bout = (const float*)d_in[8];
    float* out = (float*)d_out;

    float* vf;
    __half *Qh,*Kh,*Vh,*W1h,*W2h,*W3h,*qh,*kh,*oh;
    cudaGetSymbolAddress((void**)&vf, g_vf);
    cudaGetSymbolAddress((void**)&Qh, g_Qh);   cudaGetSymbolAddress((void**)&Kh, g_Kh);
    cudaGetSymbolAddress((void**)&Vh, g_Vh);
    cudaGetSymbolAddress((void**)&W1h, g_W1h); cudaGetSymbolAddress((void**)&W2h, g_W2h);
    cudaGetSymbolAddress((void**)&W3h, g_W3h);
    cudaGetSymbolAddress((void**)&qh, g_qh);   cudaGetSymbolAddress((void**)&kh, g_kh);
    cudaGetSymbolAddress((void**)&oh, g_oh);
    __half* vf16 = (__half*)vf;   // V projection output, fp16, flat [token][512]

    cudaFuncSetAttribute(gemm_mma, cudaFuncAttributeMaxDynamicSharedMemorySize, G_SMEM);
    cudaFuncSetAttribute(attn_mma, cudaFuncAttributeMaxDynamicSharedMemorySize, A_SMEM);

    const int TB = 256;
    cvt1x3<<<dim3(TOT/4/TB, 3), TB>>>((const float4*)Q, (uint2*)Qh,
                                      (const float4*)K, (uint2*)Kh,
                                      (const float4*)V, (uint2*)Vh);
    cvt1x3<<<dim3(EE*EE/4/TB, 3), TB>>>((const float4*)Wqk,  (uint2*)W1h,
                                        (const float4*)Wv,   (uint2*)W2h,
                                        (const float4*)Wout, (uint2*)W3h);

    const float QSC = 0.125f * 1.4426950408889634f;
    GemmArgs gp = {};
    gp.Ah[0]=Qh; gp.Wh[0]=W1h; gp.bias[0]=bqk; gp.Ch[0]=qh;   gp.scale[0]=QSC; gp.mode[0]=2;
    gp.Ah[1]=Kh; gp.Wh[1]=W1h; gp.bias[1]=bqk; gp.Ch[1]=kh;   gp.scale[1]=1.f; gp.mode[1]=2;
    gp.Ah[2]=Vh; gp.Wh[2]=W2h; gp.bias[2]=bv;  gp.Ch[2]=vf16; gp.scale[2]=1.f; gp.mode[2]=2;
    gemm_mma<<<dim3(EE/128, SQ/128, 3), TB, G_SMEM>>>(gp);

    attn_mma<<<dim3(SQ/128, HH), 128, A_SMEM>>>(qh, kh, vf16, oh);

    GemmArgs go = {};
    go.Ah[0]=oh; go.Wh[0]=W3h; go.bias[0]=bout; go.Cf[0]=out; go.scale[0]=1.f; go.mode[0]=0;
    gemm_mma<<<dim3(EE/128, SQ/128, 1), TB, G_SMEM>>>(go);
}